// round 7
// baseline (speedup 1.0000x reference)
#include <cuda_runtime.h>
#include <cuda_bf16.h>
#include <cstdint>

// ---------------- problem constants ----------------
constexpr int cB = 32768, cS = 5, cD = 512, cE = 256, cNH = 4,
              cF = 2048, cL = 2, cC = 5;
constexpr int cBS = cB * cS;               // 163840 rows
constexpr int cZK = cS * cE;               // 1280, head input dim

// ---------------- scratch (device globals; no allocs) ----------------
__device__ __align__(16) float g_H [(size_t)cBS * cE];    // residual stream fp32
__device__ __align__(16) float g_T [(size_t)cBS * 768];   // qkv fp32
__device__ __align__(16) float g_Cb[(size_t)cBS * cE];    // pre-LN gemm out fp32
__device__ __align__(16) float g_Z1[(size_t)cB * 128];
__device__ __align__(16) float g_Z2[(size_t)cB * 64];

__device__ __align__(16) __nv_bfloat16 g_Xh[(size_t)cBS * cD];
__device__ __align__(16) __nv_bfloat16 g_Xl[(size_t)cBS * cD];
__device__ __align__(16) __nv_bfloat16 g_Hh[(size_t)cBS * cE];
__device__ __align__(16) __nv_bfloat16 g_Hl[(size_t)cBS * cE];
__device__ __align__(16) __nv_bfloat16 g_Oh[(size_t)cBS * cE];
__device__ __align__(16) __nv_bfloat16 g_Ol[(size_t)cBS * cE];
__device__ __align__(16) __nv_bfloat16 g_Th[(size_t)cBS * cF];
__device__ __align__(16) __nv_bfloat16 g_Tl[(size_t)cBS * cF];

// weight hi/lo pool (element offsets)
constexpr size_t OFF_GPS = 0;                       // 256*512
constexpr size_t OFF_ANG = OFF_GPS + 131072;
constexpr size_t OFF_QKV = OFF_ANG + 131072;        // L*768*256
constexpr size_t OFF_OW  = OFF_QKV + 393216;        // L*256*256
constexpr size_t OFF_FF1 = OFF_OW  + 131072;        // L*2048*256
constexpr size_t OFF_FF2 = OFF_FF1 + 1048576;       // L*256*2048
constexpr size_t OFF_FC1 = OFF_FF2 + 1048576;       // 128*1280
constexpr size_t W_TOTAL = OFF_FC1 + 163840;
__device__ __align__(16) __nv_bfloat16 g_Wh[W_TOTAL];
__device__ __align__(16) __nv_bfloat16 g_Wl[W_TOTAL];

// =================== helpers ===================
__device__ __forceinline__ uint32_t smem_u32(const void* p) {
    uint32_t a;
    asm("{ .reg .u64 t; cvta.to.shared.u64 t, %1; cvt.u32.u64 %0, t; }"
        : "=r"(a) : "l"(p));
    return a;
}
__device__ __forceinline__ void ldsm4(uint32_t& r0, uint32_t& r1,
                                      uint32_t& r2, uint32_t& r3, uint32_t addr) {
    asm volatile("ldmatrix.sync.aligned.m8n8.x4.shared.b16 {%0,%1,%2,%3}, [%4];"
                 : "=r"(r0), "=r"(r1), "=r"(r2), "=r"(r3) : "r"(addr));
}
__device__ __forceinline__ void mma16816(float* d, const uint32_t* a,
                                         uint32_t b0, uint32_t b1) {
    asm volatile(
        "mma.sync.aligned.m16n8k16.row.col.f32.bf16.bf16.f32 "
        "{%0,%1,%2,%3}, {%4,%5,%6,%7}, {%8,%9}, {%0,%1,%2,%3};"
        : "+f"(d[0]), "+f"(d[1]), "+f"(d[2]), "+f"(d[3])
        : "r"(a[0]), "r"(a[1]), "r"(a[2]), "r"(a[3]), "r"(b0), "r"(b1));
}
__device__ __forceinline__ void cpasync16(uint32_t dst, const void* src) {
    asm volatile("cp.async.cg.shared.global [%0], [%1], 16;" :: "r"(dst), "l"(src));
}
#define CP_COMMIT() asm volatile("cp.async.commit_group;" ::: "memory")
#define CP_WAIT1()  asm volatile("cp.async.wait_group 1;" ::: "memory")

// split float2 -> hi bf162 (as u32) and lo bf162 (as u32)
__device__ __forceinline__ void split2(float x, float y, uint32_t& hi, uint32_t& lo) {
    __nv_bfloat162 h = __float22bfloat162_rn(make_float2(x, y));
    float2 hf = __bfloat1622float2(h);
    __nv_bfloat162 l = __float22bfloat162_rn(make_float2(x - hf.x, y - hf.y));
    hi = *(uint32_t*)&h;
    lo = *(uint32_t*)&l;
}
__device__ __forceinline__ void split4(float4 v, uint2& hi, uint2& lo) {
    uint32_t h0, l0, h1, l1;
    split2(v.x, v.y, h0, l0);
    split2(v.z, v.w, h1, l1);
    hi = make_uint2(h0, h1);
    lo = make_uint2(l0, l1);
}

// =================== fp32 -> bf16 hi/lo converter ===================
__global__ __launch_bounds__(256) void convert_split(
    const float* __restrict__ src, __nv_bfloat16* __restrict__ h,
    __nv_bfloat16* __restrict__ l, size_t n4)
{
    const size_t i = (size_t)blockIdx.x * blockDim.x + threadIdx.x;
    if (i >= n4) return;
    uint2 hi, lo;
    split4(((const float4*)src)[i], hi, lo);
    ((uint2*)h)[i] = hi;
    ((uint2*)l)[i] = lo;
}

constexpr int SROW = 80;                   // smem row stride bytes

// =================== BIG tensor-core GEMM: CTA 128x256, warp tile 64x64 ============
// C = (Ah+Al).(Wh+Wl)^T + bias (drops Al*Wl). M%128==0, N%256==0, K%32==0.
// Stage layout: Ah[0,10240) Al[10240,20480) Wh[20480,40960) Wl[40960,61440)
constexpr int BSTG = 61440;
constexpr int GEMM_SMEM_BIG = 2 * BSTG;    // 122880

template<bool RELU, bool PAIR>
__global__ __launch_bounds__(256) void gemm_big(
    const __nv_bfloat16* __restrict__ Ah, const __nv_bfloat16* __restrict__ Al,
    const __nv_bfloat16* __restrict__ Wh, const __nv_bfloat16* __restrict__ Wl,
    const float* __restrict__ bias,
    float* __restrict__ Cf,
    __nv_bfloat16* __restrict__ Ch, __nv_bfloat16* __restrict__ Cl,
    int M, int N, int K)
{
    extern __shared__ char sm[];
    const uint32_t sbase = smem_u32(sm);

    const int tid = threadIdx.x;
    const int wid = tid >> 5, lane = tid & 31;
    const int bm = blockIdx.y * 128, bn = blockIdx.x * 256;
    const int wm = (wid >> 2) * 64, wn = (wid & 3) * 64;

    // loader: thread -> row r = tid/4 (0..63), 16B quarter q = tid&3
    const int r = tid >> 2, q = tid & 3;
    const __nv_bfloat16* pAh = Ah + (size_t)(bm + r) * K + q * 8;
    const __nv_bfloat16* pAl = Al + (size_t)(bm + r) * K + q * 8;
    const __nv_bfloat16* pWh = Wh + (size_t)(bn + r) * K + q * 8;
    const __nv_bfloat16* pWl = Wl + (size_t)(bn + r) * K + q * 8;
    const size_t K64 = (size_t)64 * K;
    const uint32_t soff = (uint32_t)(r * SROW + q * 16);

    auto issue_stage = [&](int c, int s) {
        const uint32_t st = sbase + s * BSTG + soff;
        const size_t ko = (size_t)c * 32;
        cpasync16(st,                 pAh + ko);
        cpasync16(st + 64*SROW,       pAh + ko + K64);
        cpasync16(st + 10240,         pAl + ko);
        cpasync16(st + 10240+64*SROW, pAl + ko + K64);
#pragma unroll
        for (int j = 0; j < 4; j++)
            cpasync16(st + 20480 + j * (64*SROW), pWh + ko + j * K64);
#pragma unroll
        for (int j = 0; j < 4; j++)
            cpasync16(st + 40960 + j * (64*SROW), pWl + ko + j * K64);
    };

    float acc[4][8][4];
#pragma unroll
    for (int i = 0; i < 4; i++)
#pragma unroll
        for (int j = 0; j < 8; j++)
#pragma unroll
            for (int k = 0; k < 4; k++) acc[i][j][k] = 0.f;

    const uint32_t a_off = (uint32_t)((wm + (lane & 15)) * SROW + (lane >> 4) * 16);
    const uint32_t w_off = (uint32_t)((wn + (lane & 7) + ((lane >> 4) & 1) * 8) * SROW
                                      + ((lane >> 3) & 1) * 16);

    const int nk = K / 32;
    issue_stage(0, 0); CP_COMMIT();
    if (nk > 1) issue_stage(1, 1);
    CP_COMMIT();

    for (int c = 0; c < nk; ++c) {
        const int s = c & 1;
        CP_WAIT1();
        __syncthreads();

        const uint32_t sAh = sbase + s * BSTG;
        const uint32_t sAl = sAh + 10240;
        const uint32_t sWh = sAh + 20480;
        const uint32_t sWl = sAh + 40960;

#pragma unroll
        for (int ks = 0; ks < 2; ++ks) {
            const uint32_t ko = ks * 32;
            uint32_t aF[4][4], bF[8][2];
#pragma unroll
            for (int mf = 0; mf < 4; mf++)
                ldsm4(aF[mf][0], aF[mf][1], aF[mf][2], aF[mf][3],
                      sAh + a_off + mf * (16 * SROW) + ko);
#pragma unroll
            for (int p = 0; p < 4; p++) {
                uint32_t r0, r1, r2, r3;
                ldsm4(r0, r1, r2, r3, sWh + w_off + p * (16 * SROW) + ko);
                bF[2*p][0] = r0; bF[2*p][1] = r1;
                bF[2*p+1][0] = r2; bF[2*p+1][1] = r3;
            }
            // pass 1: Ah * Wh
#pragma unroll
            for (int mf = 0; mf < 4; mf++)
#pragma unroll
                for (int nf = 0; nf < 8; nf++)
                    mma16816(acc[mf][nf], aF[mf], bF[nf][0], bF[nf][1]);
            // pass 2: Ah * Wl (transient 4 regs per p)
#pragma unroll
            for (int p = 0; p < 4; p++) {
                uint32_t c0, c1, c2, c3;
                ldsm4(c0, c1, c2, c3, sWl + w_off + p * (16 * SROW) + ko);
#pragma unroll
                for (int mf = 0; mf < 4; mf++) {
                    mma16816(acc[mf][2*p],   aF[mf], c0, c1);
                    mma16816(acc[mf][2*p+1], aF[mf], c2, c3);
                }
            }
            // pass 3: Al * Wh (transient 4 regs per mf)
#pragma unroll
            for (int mf = 0; mf < 4; mf++) {
                uint32_t e[4];
                ldsm4(e[0], e[1], e[2], e[3],
                      sAl + a_off + mf * (16 * SROW) + ko);
#pragma unroll
                for (int nf = 0; nf < 8; nf++)
                    mma16816(acc[mf][nf], e, bF[nf][0], bF[nf][1]);
            }
        }
        __syncthreads();
        if (c + 2 < nk) issue_stage(c + 2, s);
        CP_COMMIT();
    }

    // epilogue
    const int erow = (lane >> 2);
    const int ecol = (lane & 3) * 2;
#pragma unroll
    for (int nf = 0; nf < 8; nf++) {
        const int col = bn + wn + nf * 8 + ecol;
        const float2 bv = *(const float2*)&bias[col];
#pragma unroll
        for (int mf = 0; mf < 4; mf++) {
            const int r0 = bm + wm + mf * 16 + erow;
            float2 o0, o1;
            o0.x = acc[mf][nf][0] + bv.x; o0.y = acc[mf][nf][1] + bv.y;
            o1.x = acc[mf][nf][2] + bv.x; o1.y = acc[mf][nf][3] + bv.y;
            if (RELU) {
                o0.x = fmaxf(o0.x, 0.f); o0.y = fmaxf(o0.y, 0.f);
                o1.x = fmaxf(o1.x, 0.f); o1.y = fmaxf(o1.y, 0.f);
            }
            if (PAIR) {
                uint32_t h, l;
                split2(o0.x, o0.y, h, l);
                *(uint32_t*)&Ch[(size_t)r0 * N + col] = h;
                *(uint32_t*)&Cl[(size_t)r0 * N + col] = l;
                split2(o1.x, o1.y, h, l);
                *(uint32_t*)&Ch[(size_t)(r0 + 8) * N + col] = h;
                *(uint32_t*)&Cl[(size_t)(r0 + 8) * N + col] = l;
            } else {
                *(float2*)&Cf[(size_t)r0 * N + col] = o0;
                *(float2*)&Cf[(size_t)(r0 + 8) * N + col] = o1;
            }
        }
    }
}

// =================== small tensor-core GEMM (fc1, N=128): CTA 128x128 =============
constexpr int SBUF = 128 * SROW;           // 10240
constexpr int STAGE_B = 4 * SBUF;          // 40960
constexpr int GEMM_SMEM = 2 * STAGE_B;     // 81920

__global__ __launch_bounds__(256) void gemm_sm(
    const __nv_bfloat16* __restrict__ Ah, const __nv_bfloat16* __restrict__ Al,
    const __nv_bfloat16* __restrict__ Wh, const __nv_bfloat16* __restrict__ Wl,
    const float* __restrict__ bias, float* __restrict__ Cf,
    int M, int N, int K)
{
    extern __shared__ char sm[];
    const uint32_t sbase = smem_u32(sm);

    const int tid = threadIdx.x;
    const int wid = tid >> 5, lane = tid & 31;
    const int bm = blockIdx.y * 128, bn = blockIdx.x * 128;
    const int wm = (wid & 1) * 64, wn = (wid >> 1) * 32;

    const int lrow = tid >> 1;
    const int q0 = (tid & 1) * 2;
    const __nv_bfloat16* pAh = Ah + (size_t)(bm + lrow) * K + q0 * 8;
    const __nv_bfloat16* pAl = Al + (size_t)(bm + lrow) * K + q0 * 8;
    const __nv_bfloat16* pWh = Wh + (size_t)(bn + lrow) * K + q0 * 8;
    const __nv_bfloat16* pWl = Wl + (size_t)(bn + lrow) * K + q0 * 8;
    const uint32_t soff = (uint32_t)(lrow * SROW + q0 * 16);

    auto issue_stage = [&](int c, int s) {
        const uint32_t st = sbase + s * STAGE_B + soff;
        const size_t ko = (size_t)c * 32;
        cpasync16(st,                pAh + ko);
        cpasync16(st + 16,           pAh + ko + 8);
        cpasync16(st + SBUF,         pAl + ko);
        cpasync16(st + SBUF + 16,    pAl + ko + 8);
        cpasync16(st + 2*SBUF,       pWh + ko);
        cpasync16(st + 2*SBUF + 16,  pWh + ko + 8);
        cpasync16(st + 3*SBUF,       pWl + ko);
        cpasync16(st + 3*SBUF + 16,  pWl + ko + 8);
    };

    float acc[4][4][4];
#pragma unroll
    for (int i = 0; i < 4; i++)
#pragma unroll
        for (int j = 0; j < 4; j++)
#pragma unroll
            for (int k = 0; k < 4; k++) acc[i][j][k] = 0.f;

    const uint32_t a_off = (uint32_t)((wm + (lane & 15)) * SROW + (lane >> 4) * 16);
    const uint32_t w_off = (uint32_t)((wn + (lane & 7) + ((lane >> 4) & 1) * 8) * SROW
                                      + ((lane >> 3) & 1) * 16);

    const int nk = K / 32;
    issue_stage(0, 0); CP_COMMIT();
    if (nk > 1) issue_stage(1, 1);
    CP_COMMIT();

    for (int c = 0; c < nk; ++c) {
        const int s = c & 1;
        CP_WAIT1();
        __syncthreads();
        const uint32_t sAh = sbase + s * STAGE_B;
        const uint32_t sAl = sAh + SBUF;
        const uint32_t sWh = sAh + 2 * SBUF;
        const uint32_t sWl = sAh + 3 * SBUF;
#pragma unroll
        for (int ks = 0; ks < 2; ++ks) {
            const uint32_t ko = ks * 32;
            uint32_t aF[4][4], bF[4][2];
#pragma unroll
            for (int mf = 0; mf < 4; mf++)
                ldsm4(aF[mf][0], aF[mf][1], aF[mf][2], aF[mf][3],
                      sAh + a_off + mf * (16 * SROW) + ko);
#pragma unroll
            for (int p = 0; p < 2; p++) {
                uint32_t r0, r1, r2, r3;
                ldsm4(r0, r1, r2, r3, sWh + w_off + p * (16 * SROW) + ko);
                bF[2*p][0] = r0; bF[2*p][1] = r1;
                bF[2*p+1][0] = r2; bF[2*p+1][1] = r3;
            }
#pragma unroll
            for (int mf = 0; mf < 4; mf++)
#pragma unroll
                for (int nf = 0; nf < 4; nf++)
                    mma16816(acc[mf][nf], aF[mf], bF[nf][0], bF[nf][1]);
#pragma unroll
            for (int p = 0; p < 2; p++) {
                uint32_t c0, c1, c2, c3;
                ldsm4(c0, c1, c2, c3, sWl + w_off + p * (16 * SROW) + ko);
#pragma unroll
                for (int mf = 0; mf < 4; mf++) {
                    mma16816(acc[mf][2*p],   aF[mf], c0, c1);
                    mma16816(acc[mf][2*p+1], aF[mf], c2, c3);
                }
            }
#pragma unroll
            for (int mf = 0; mf < 4; mf++) {
                uint32_t e[4];
                ldsm4(e[0], e[1], e[2], e[3], sAl + a_off + mf * (16 * SROW) + ko);
#pragma unroll
                for (int nf = 0; nf < 4; nf++)
                    mma16816(acc[mf][nf], e, bF[nf][0], bF[nf][1]);
            }
        }
        __syncthreads();
        if (c + 2 < nk) issue_stage(c + 2, s);
        CP_COMMIT();
    }

    const int erow = (lane >> 2);
    const int ecol = (lane & 3) * 2;
#pragma unroll
    for (int nf = 0; nf < 4; nf++) {
        const int col = bn + wn + nf * 8 + ecol;
        const float2 bv = *(const float2*)&bias[col];
#pragma unroll
        for (int mf = 0; mf < 4; mf++) {
            const int r0 = bm + wm + mf * 16 + erow;
            float2 o0, o1;
            o0.x = acc[mf][nf][0] + bv.x; o0.y = acc[mf][nf][1] + bv.y;
            o1.x = acc[mf][nf][2] + bv.x; o1.y = acc[mf][nf][3] + bv.y;
            *(float2*)&Cf[(size_t)r0 * N + col] = o0;
            *(float2*)&Cf[(size_t)(r0 + 8) * N + col] = o1;
        }
    }
}

// =================== small SIMT GEMM (head fc2) ===================
__global__ __launch_bounds__(256) void gemm_bias(
    const float* __restrict__ A, const float* __restrict__ W,
    const float* __restrict__ bias, float* __restrict__ C,
    int M, int N, int K)
{
    __shared__ float As[16][68];
    __shared__ float Ws[16][68];
    const int t  = threadIdx.x;
    const int bm = blockIdx.y * 64, bn = blockIdx.x * 64;
    const int tm = (t >> 4) << 2;
    const int tn = (t & 15) << 2;
    const int lr = t >> 2;
    const int lc = (t & 3) << 2;

    float acc[4][4] = {};
    const float* Ap = A + (size_t)(bm + lr) * K + lc;
    const float* Wp = W + (size_t)(bn + lr) * K + lc;

    for (int k0 = 0; k0 < K; k0 += 16) {
        float4 av = *(const float4*)(Ap + k0);
        float4 wv = (bn + lr < N) ? *(const float4*)(Wp + k0) : make_float4(0, 0, 0, 0);
        As[lc+0][lr]=av.x; As[lc+1][lr]=av.y; As[lc+2][lr]=av.z; As[lc+3][lr]=av.w;
        Ws[lc+0][lr]=wv.x; Ws[lc+1][lr]=wv.y; Ws[lc+2][lr]=wv.z; Ws[lc+3][lr]=wv.w;
        __syncthreads();
#pragma unroll
        for (int k = 0; k < 16; k++) {
            float4 a4 = *(const float4*)&As[k][tm];
            float4 w4 = *(const float4*)&Ws[k][tn];
            const float ar[4] = {a4.x, a4.y, a4.z, a4.w};
            const float wr[4] = {w4.x, w4.y, w4.z, w4.w};
#pragma unroll
            for (int r = 0; r < 4; r++)
#pragma unroll
                for (int c = 0; c < 4; c++)
                    acc[r][c] = fmaf(ar[r], wr[c], acc[r][c]);
        }
        __syncthreads();
    }
    if (bn + tn >= N) return;
    float4 bv = *(const float4*)&bias[bn + tn];
    const float bb[4] = {bv.x, bv.y, bv.z, bv.w};
#pragma unroll
    for (int r = 0; r < 4; r++) {
        float4 o; float* op = (float*)&o;
#pragma unroll
        for (int c = 0; c < 4; c++) op[c] = acc[r][c] + bb[c];
        *(float4*)&C[(size_t)(bm + tm + r) * N + bn + tn] = o;
    }
}

// =================== expert select (fp32 in, fp32 + bf16 pair out) ===================
__global__ __launch_bounds__(256) void select_kernel(
    const float* __restrict__ G, const float* __restrict__ A2,
    const int* __restrict__ ST, float* __restrict__ H,
    __nv_bfloat16* __restrict__ Hh, __nv_bfloat16* __restrict__ Hl)
{
    const size_t i = (size_t)blockIdx.x * blockDim.x + threadIdx.x;  // float4 idx
    const int row = (int)(i >> 6);                                   // 64 float4/row
    const float4 v = (ST[row] == 0) ? ((const float4*)G)[i] : ((const float4*)A2)[i];
    ((float4*)H)[i] = v;
    uint2 hi, lo;
    split4(v, hi, lo);
    ((uint2*)Hh)[i] = hi;
    ((uint2*)Hl)[i] = lo;
}

// =================== attention: one warp per (batch, head), bf16-pair out ===========
__global__ __launch_bounds__(256) void attn_kernel(
    const float* __restrict__ QKV,
    __nv_bfloat16* __restrict__ Oh, __nv_bfloat16* __restrict__ Ol)
{
    const int gwarp = (blockIdx.x * blockDim.x + threadIdx.x) >> 5;
    const int lane  = threadIdx.x & 31;
    if (gwarp >= cB * cNH) return;
    const int b = gwarp >> 2, h = gwarp & 3;

    const float* base = QKV + (size_t)b * cS * 768 + h * 64 + 2 * lane;
    float q[cS][2], kk[cS][2], vv[cS][2];
#pragma unroll
    for (int s = 0; s < cS; s++) {
        const float* r = base + s * 768;
        float2 qv = *(const float2*)(r);
        float2 kv = *(const float2*)(r + 256);
        float2 vw = *(const float2*)(r + 512);
        q [s][0] = qv.x; q [s][1] = qv.y;
        kk[s][0] = kv.x; kk[s][1] = kv.y;
        vv[s][0] = vw.x; vv[s][1] = vw.y;
    }
    float sc[cS][cS];
#pragma unroll
    for (int i = 0; i < cS; i++)
#pragma unroll
        for (int j = 0; j < cS; j++) {
            float p = q[i][0] * kk[j][0] + q[i][1] * kk[j][1];
#pragma unroll
            for (int o = 16; o > 0; o >>= 1) p += __shfl_xor_sync(0xFFFFFFFFu, p, o);
            sc[i][j] = p * 0.125f;
        }
#pragma unroll
    for (int i = 0; i < cS; i++) {
        float m = sc[i][0];
#pragma unroll
        for (int j = 1; j < cS; j++) m = fmaxf(m, sc[i][j]);
        float e[cS], s = 0.f;
#pragma unroll
        for (int j = 0; j < cS; j++) { e[j] = expf(sc[i][j] - m); s += e[j]; }
        const float inv = 1.f / s;
        float o0 = 0.f, o1 = 0.f;
#pragma unroll
        for (int j = 0; j < cS; j++) {
            const float a = e[j] * inv;
            o0 = fmaf(a, vv[j][0], o0);
            o1 = fmaf(a, vv[j][1], o1);
        }
        uint32_t hi, lo;
        split2(o0, o1, hi, lo);
        const size_t off = (size_t)(b * cS + i) * cE + h * 64 + 2 * lane;
        *(uint32_t*)&Oh[off] = hi;
        *(uint32_t*)&Ol[off] = lo;
    }
}

// =================== fused residual + layernorm (fp32 + bf16-pair out) ===============
__global__ __launch_bounds__(256) void add_ln_kernel(
    const float* __restrict__ Hin, const float* __restrict__ Cin,
    const float* __restrict__ G, const float* __restrict__ Bv,
    float* __restrict__ Hout,
    __nv_bfloat16* __restrict__ Hh, __nv_bfloat16* __restrict__ Hl)
{
    const int row  = blockIdx.x * 8 + (threadIdx.x >> 5);
    const int lane = threadIdx.x & 31;
    const size_t rb = (size_t)row * cE;

    float2 v[4];
    float s = 0.f;
#pragma unroll
    for (int i = 0; i < 4; i++) {
        const int e = i * 64 + lane * 2;
        float2 a = *(const float2*)&Hin[rb + e];
        float2 b = *(const float2*)&Cin[rb + e];
        v[i].x = a.x + b.x; v[i].y = a.y + b.y;
        s += v[i].x + v[i].y;
    }
#pragma unroll
    for (int o = 16; o > 0; o >>= 1) s += __shfl_xor_sync(0xFFFFFFFFu, s, o);
    const float mean = s * (1.f / cE);

    float vs = 0.f;
#pragma unroll
    for (int i = 0; i < 4; i++) {
        const float dx = v[i].x - mean, dy = v[i].y - mean;
        vs += dx * dx + dy * dy;
    }
#pragma unroll
    for (int o = 16; o > 0; o >>= 1) vs += __shfl_xor_sync(0xFFFFFFFFu, vs, o);
    const float rs = rsqrtf(vs * (1.f / cE) + 1e-5f);

#pragma unroll
    for (int i = 0; i < 4; i++) {
        const int e = i * 64 + lane * 2;
        const float2 g = *(const float2*)&G[e];
        const float2 b = *(const float2*)&Bv[e];
        float2 o;
        o.x = (v[i].x - mean) * rs * g.x + b.x;
        o.y = (v[i].y - mean) * rs * g.y + b.y;
        *(float2*)&Hout[rb + e] = o;
        uint32_t hi, lo;
        split2(o.x, o.y, hi, lo);
        *(uint32_t*)&Hh[rb + e] = hi;
        *(uint32_t*)&Hl[rb + e] = lo;
    }
}

// =================== final tiny projection ===================
__global__ __launch_bounds__(256) void out_kernel(
    const float* __restrict__ Z, const float* __restrict__ OW,
    const float* __restrict__ OB, float* __restrict__ OUT)
{
    const int b = blockIdx.x * blockDim.x + threadIdx.x;
    if (b >= cB) return;
    float acc[cC];
#pragma unroll
    for (int c = 0; c < cC; c++) acc[c] = OB[c];
    const float* zr = Z + (size_t)b * 64;
    for (int k = 0; k < 64; k++) {
        const float z = zr[k];
#pragma unroll
        for (int c = 0; c < cC; c++) acc[c] = fmaf(z, OW[c * 64 + k], acc[c]);
    }
#pragma unroll
    for (int c = 0; c < cC; c++) OUT[(size_t)b * cC + c] = acc[c];
}

// ---------------- launch ----------------
template<typename T>
static T* symaddr(const void* sym) {
    void* p = nullptr;
    cudaGetSymbolAddress(&p, sym);
    return (T*)p;
}
static void conv(const float* src, __nv_bfloat16* h, __nv_bfloat16* l, size_t n) {
    const size_t n4 = n / 4;
    convert_split<<<(unsigned)((n4 + 255) / 256), 256>>>(src, h, l, n4);
}

extern "C" void kernel_launch(void* const* d_in, const int* in_sizes, int n_in,
                              void* d_out, int out_size)
{
    const float* x       = (const float*)d_in[0];
    const int*   st      = (const int*)  d_in[1];
    const float* gps_w   = (const float*)d_in[2];
    const float* gps_b   = (const float*)d_in[3];
    const float* ang_w   = (const float*)d_in[4];
    const float* ang_b   = (const float*)d_in[5];
    const float* qkv_w   = (const float*)d_in[6];
    const float* qkv_b   = (const float*)d_in[7];
    const float* attn_ow = (const float*)d_in[8];
    const float* attn_ob = (const float*)d_in[9];
    const float* ln1_g   = (const float*)d_in[10];
    const float* ln1_b   = (const float*)d_in[11];
    const float* ff1_w   = (const float*)d_in[12];
    const float* ff1_b   = (const float*)d_in[13];
    const float* ff2_w   = (const float*)d_in[14];
    const float* ff2_b   = (const float*)d_in[15];
    const float* ln2_g   = (const float*)d_in[16];
    const float* ln2_b   = (const float*)d_in[17];
    const float* fc1_w   = (const float*)d_in[18];
    const float* fc1_b   = (const float*)d_in[19];
    const float* fc2_w   = (const float*)d_in[20];
    const float* fc2_b   = (const float*)d_in[21];
    const float* out_w   = (const float*)d_in[22];
    const float* out_b   = (const float*)d_in[23];
    float* out = (float*)d_out;

    float* H  = symaddr<float>(g_H);
    float* T  = symaddr<float>(g_T);
    float* Cb = symaddr<float>(g_Cb);
    float* Z1 = symaddr<float>(g_Z1);
    float* Z2 = symaddr<float>(g_Z2);
    __nv_bfloat16* Xh = symaddr<__nv_bfloat16>(g_Xh);
    __nv_bfloat16* Xl = symaddr<__nv_bfloat16>(g_Xl);
    __nv_bfloat16* Hh = symaddr<__nv_bfloat16>(g_Hh);
    __nv_bfloat16* Hl = symaddr<__nv_bfloat16>(g_Hl);
    __nv_bfloat16* Oh = symaddr<__nv_bfloat16>(g_Oh);
    __nv_bfloat16* Ol = symaddr<__nv_bfloat16>(g_Ol);
    __nv_bfloat16* Th = symaddr<__nv_bfloat16>(g_Th);
    __nv_bfloat16* Tl = symaddr<__nv_bfloat16>(g_Tl);
    __nv_bfloat16* Wh = symaddr<__nv_bfloat16>(g_Wh);
    __nv_bfloat16* Wl = symaddr<__nv_bfloat16>(g_Wl);

    static bool attr_set = false;
    if (!attr_set) {
        cudaFuncSetAttribute((const void*)gemm_big<false,false>,
                             cudaFuncAttributeMaxDynamicSharedMemorySize, GEMM_SMEM_BIG);
        cudaFuncSetAttribute((const void*)gemm_big<true,false>,
                             cudaFuncAttributeMaxDynamicSharedMemorySize, GEMM_SMEM_BIG);
        cudaFuncSetAttribute((const void*)gemm_big<true,true>,
                             cudaFuncAttributeMaxDynamicSharedMemorySize, GEMM_SMEM_BIG);
        cudaFuncSetAttribute((const void*)gemm_sm,
                             cudaFuncAttributeMaxDynamicSharedMemorySize, GEMM_SMEM);
        attr_set = true;
    }

    // 0. convert inputs + weights to bf16 hi/lo
    conv(x, Xh, Xl, (size_t)cBS * cD);
    conv(gps_w,   Wh + OFF_GPS, Wl + OFF_GPS, 131072);
    conv(ang_w,   Wh + OFF_ANG, Wl + OFF_ANG, 131072);
    conv(qkv_w,   Wh + OFF_QKV, Wl + OFF_QKV, 393216);
    conv(attn_ow, Wh + OFF_OW,  Wl + OFF_OW,  131072);
    conv(ff1_w,   Wh + OFF_FF1, Wl + OFF_FF1, 1048576);
    conv(ff2_w,   Wh + OFF_FF2, Wl + OFF_FF2, 1048576);
    conv(fc1_w,   Wh + OFF_FC1, Wl + OFF_FC1, 163840);

    const int MT = cBS / 128;   // 1280 row tiles
    float* G  = T;                      // expert outputs (fp32 scratch)
    float* A2 = T + (size_t)cBS * cE;   // fits in g_T ([BS,768])

    // 1. dual-expert embed + select
    gemm_big<true,false><<<dim3(1, MT), 256, GEMM_SMEM_BIG>>>(
        Xh, Xl, Wh + OFF_GPS, Wl + OFF_GPS, gps_b, G, nullptr, nullptr, cBS, cE, cD);
    gemm_big<true,false><<<dim3(1, MT), 256, GEMM_SMEM_BIG>>>(
        Xh, Xl, Wh + OFF_ANG, Wl + OFF_ANG, ang_b, A2, nullptr, nullptr, cBS, cE, cD);
    select_kernel<<<(cBS * cE / 4) / 256, 256>>>(G, A2, st, H, Hh, Hl);

    // 2. transformer layers
    for (int l = 0; l < cL; l++) {
        const __nv_bfloat16* qwh = Wh + OFF_QKV + (size_t)l * 768 * cE;
        const __nv_bfloat16* qwl = Wl + OFF_QKV + (size_t)l * 768 * cE;
        const __nv_bfloat16* owh = Wh + OFF_OW  + (size_t)l * cE * cE;
        const __nv_bfloat16* owl = Wl + OFF_OW  + (size_t)l * cE * cE;
        const __nv_bfloat16* f1h = Wh + OFF_FF1 + (size_t)l * cF * cE;
        const __nv_bfloat16* f1l = Wl + OFF_FF1 + (size_t)l * cF * cE;
        const __nv_bfloat16* f2h = Wh + OFF_FF2 + (size_t)l * cE * cF;
        const __nv_bfloat16* f2l = Wl + OFF_FF2 + (size_t)l * cE * cF;
        const float* qb  = qkv_b   + (size_t)l * 3 * cE;
        const float* ob  = attn_ob + (size_t)l * cE;
        const float* f1b = ff1_b   + (size_t)l * cF;
        const float* f2b = ff2_b   + (size_t)l * cE;

        gemm_big<false,false><<<dim3(768/256, MT), 256, GEMM_SMEM_BIG>>>(
            Hh, Hl, qwh, qwl, qb, T, nullptr, nullptr, cBS, 768, cE);
        attn_kernel<<<(cB * cNH * 32) / 256, 256>>>(T, Oh, Ol);
        gemm_big<false,false><<<dim3(1, MT), 256, GEMM_SMEM_BIG>>>(
            Oh, Ol, owh, owl, ob, Cb, nullptr, nullptr, cBS, cE, cE);
        add_ln_kernel<<<cBS / 8, 256>>>(H, Cb, ln1_g + l * cE, ln1_b + l * cE, H, Hh, Hl);
        gemm_big<true,true><<<dim3(cF/256, MT), 256, GEMM_SMEM_BIG>>>(
            Hh, Hl, f1h, f1l, f1b, nullptr, Th, Tl, cBS, cF, cE);
        gemm_big<false,false><<<dim3(1, MT), 256, GEMM_SMEM_BIG>>>(
            Th, Tl, f2h, f2l, f2b, Cb, nullptr, nullptr, cBS, cE, cF);
        add_ln_kernel<<<cBS / 8, 256>>>(H, Cb, ln2_g + l * cE, ln2_b + l * cE, H, Hh, Hl);
    }

    // 3. head: Hh/Hl viewed as [B,1280]
    gemm_sm<<<dim3(1, cB/128), 256, GEMM_SMEM>>>(
        Hh, Hl, Wh + OFF_FC1, Wl + OFF_FC1, fc1_b, Z1, cB, 128, cZK);
    gemm_bias<<<dim3(1, cB/64), 256>>>(Z1, fc2_w, fc2_b, Z2, cB, 64, 128);
    out_kernel<<<cB / 256, 256>>>(Z2, out_w, out_b, out);
}

// round 9
// speedup vs baseline: 1.1076x; 1.1076x over previous
#include <cuda_runtime.h>
#include <cuda_bf16.h>
#include <cstdint>

// ---------------- problem constants ----------------
constexpr int cB = 32768, cS = 5, cD = 512, cE = 256, cNH = 4,
              cF = 2048, cL = 2, cC = 5;
constexpr int cBS = cB * cS;               // 163840 rows
constexpr int cZK = cS * cE;               // 1280, head input dim

// ---------------- scratch (device globals; no allocs) ----------------
__device__ __align__(16) float g_H [(size_t)cBS * cE];    // residual stream fp32
__device__ __align__(16) float g_T [(size_t)cBS * 768];   // qkv fp32
__device__ __align__(16) float g_Cb[(size_t)cBS * cE];    // pre-LN gemm out fp32
__device__ __align__(16) float g_Z1[(size_t)cB * 128];
__device__ __align__(16) float g_Z2[(size_t)cB * 64];

__device__ __align__(16) __nv_bfloat16 g_Xh[(size_t)cBS * cD];
__device__ __align__(16) __nv_bfloat16 g_Xl[(size_t)cBS * cD];
__device__ __align__(16) __nv_bfloat16 g_Hh[(size_t)cBS * cE];
__device__ __align__(16) __nv_bfloat16 g_Hl[(size_t)cBS * cE];
__device__ __align__(16) __nv_bfloat16 g_Oh[(size_t)cBS * cE];
__device__ __align__(16) __nv_bfloat16 g_Ol[(size_t)cBS * cE];
__device__ __align__(16) __nv_bfloat16 g_Th[(size_t)cBS * cF];
__device__ __align__(16) __nv_bfloat16 g_Tl[(size_t)cBS * cF];

// weight hi/lo pool (element offsets)
constexpr size_t OFF_GPS = 0;                       // 256*512
constexpr size_t OFF_ANG = OFF_GPS + 131072;
constexpr size_t OFF_QKV = OFF_ANG + 131072;        // L*768*256
constexpr size_t OFF_OW  = OFF_QKV + 393216;        // L*256*256
constexpr size_t OFF_FF1 = OFF_OW  + 131072;        // L*2048*256
constexpr size_t OFF_FF2 = OFF_FF1 + 1048576;       // L*256*2048
constexpr size_t OFF_FC1 = OFF_FF2 + 1048576;       // 128*1280
constexpr size_t W_TOTAL = OFF_FC1 + 163840;
__device__ __align__(16) __nv_bfloat16 g_Wh[W_TOTAL];
__device__ __align__(16) __nv_bfloat16 g_Wl[W_TOTAL];

// =================== helpers ===================
__device__ __forceinline__ uint32_t smem_u32(const void* p) {
    uint32_t a;
    asm("{ .reg .u64 t; cvta.to.shared.u64 t, %1; cvt.u32.u64 %0, t; }"
        : "=r"(a) : "l"(p));
    return a;
}
__device__ __forceinline__ void ldsm4(uint32_t& r0, uint32_t& r1,
                                      uint32_t& r2, uint32_t& r3, uint32_t addr) {
    asm volatile("ldmatrix.sync.aligned.m8n8.x4.shared.b16 {%0,%1,%2,%3}, [%4];"
                 : "=r"(r0), "=r"(r1), "=r"(r2), "=r"(r3) : "r"(addr));
}
__device__ __forceinline__ void mma16816(float* d, const uint32_t* a,
                                         uint32_t b0, uint32_t b1) {
    asm volatile(
        "mma.sync.aligned.m16n8k16.row.col.f32.bf16.bf16.f32 "
        "{%0,%1,%2,%3}, {%4,%5,%6,%7}, {%8,%9}, {%0,%1,%2,%3};"
        : "+f"(d[0]), "+f"(d[1]), "+f"(d[2]), "+f"(d[3])
        : "r"(a[0]), "r"(a[1]), "r"(a[2]), "r"(a[3]), "r"(b0), "r"(b1));
}
__device__ __forceinline__ void cpasync16(uint32_t dst, const void* src) {
    asm volatile("cp.async.cg.shared.global [%0], [%1], 16;" :: "r"(dst), "l"(src));
}
#define CP_COMMIT() asm volatile("cp.async.commit_group;" ::: "memory")
#define CP_WAIT1()  asm volatile("cp.async.wait_group 1;" ::: "memory")

// split float2 -> hi bf162 (as u32) and lo bf162 (as u32)
__device__ __forceinline__ void split2(float x, float y, uint32_t& hi, uint32_t& lo) {
    __nv_bfloat162 h = __float22bfloat162_rn(make_float2(x, y));
    float2 hf = __bfloat1622float2(h);
    __nv_bfloat162 l = __float22bfloat162_rn(make_float2(x - hf.x, y - hf.y));
    hi = *(uint32_t*)&h;
    lo = *(uint32_t*)&l;
}
__device__ __forceinline__ void split4(float4 v, uint2& hi, uint2& lo) {
    uint32_t h0, l0, h1, l1;
    split2(v.x, v.y, h0, l0);
    split2(v.z, v.w, h1, l1);
    hi = make_uint2(h0, h1);
    lo = make_uint2(l0, l1);
}

// =================== fp32 -> bf16 hi/lo converter ===================
__global__ __launch_bounds__(256) void convert_split(
    const float* __restrict__ src, __nv_bfloat16* __restrict__ h,
    __nv_bfloat16* __restrict__ l, size_t n4)
{
    const size_t i = (size_t)blockIdx.x * blockDim.x + threadIdx.x;
    if (i >= n4) return;
    uint2 hi, lo;
    split4(((const float4*)src)[i], hi, lo);
    ((uint2*)h)[i] = hi;
    ((uint2*)l)[i] = lo;
}

// =================== tensor-core GEMM: CTA 128x128, warp tile 32x64 ================
// 8 warps as 4(M) x 2(N). acc = 64 regs/thread -> 2 CTAs/SM (16 warps).
// C = (Ah+Al).(Wh+Wl)^T + bias (drops Al*Wl). M%128==0, N%128==0, K%32==0.
constexpr int SROW = 80;                   // smem row stride (bytes)
constexpr int SBUF = 128 * SROW;           // 10240 B per operand
constexpr int STAGE_B = 4 * SBUF;          // 40960 B per stage (Ah,Al,Wh,Wl)
constexpr int GEMM_SMEM = 2 * STAGE_B;     // 81920 B

template<bool RELU, bool PAIR>
__global__ __launch_bounds__(256, 2) void gemm_mma(
    const __nv_bfloat16* __restrict__ Ah, const __nv_bfloat16* __restrict__ Al,
    const __nv_bfloat16* __restrict__ Wh, const __nv_bfloat16* __restrict__ Wl,
    const float* __restrict__ bias,
    float* __restrict__ Cf,
    __nv_bfloat16* __restrict__ Ch, __nv_bfloat16* __restrict__ Cl,
    int M, int N, int K)
{
    extern __shared__ char sm[];
    const uint32_t sbase = smem_u32(sm);

    const int tid = threadIdx.x;
    const int wid = tid >> 5, lane = tid & 31;
    const int bm = blockIdx.y * 128, bn = blockIdx.x * 128;
    const int wm = (wid >> 1) * 32, wn = (wid & 1) * 64;

    // loader: thread -> row tid/2 (0..127), 16B chunks q0, q0+1 where q0=(tid&1)*2
    const int lrow = tid >> 1;
    const int q0 = (tid & 1) * 2;
    const __nv_bfloat16* pAh = Ah + (size_t)(bm + lrow) * K + q0 * 8;
    const __nv_bfloat16* pAl = Al + (size_t)(bm + lrow) * K + q0 * 8;
    const __nv_bfloat16* pWh = Wh + (size_t)(bn + lrow) * K + q0 * 8;
    const __nv_bfloat16* pWl = Wl + (size_t)(bn + lrow) * K + q0 * 8;
    const uint32_t soff = (uint32_t)(lrow * SROW + q0 * 16);

    auto issue_stage = [&](int c, int s) {
        const uint32_t st = sbase + s * STAGE_B + soff;
        const size_t ko = (size_t)c * 32;
        cpasync16(st,                pAh + ko);
        cpasync16(st + 16,           pAh + ko + 8);
        cpasync16(st + SBUF,         pAl + ko);
        cpasync16(st + SBUF + 16,    pAl + ko + 8);
        cpasync16(st + 2*SBUF,       pWh + ko);
        cpasync16(st + 2*SBUF + 16,  pWh + ko + 8);
        cpasync16(st + 3*SBUF,       pWl + ko);
        cpasync16(st + 3*SBUF + 16,  pWl + ko + 8);
    };

    float acc[2][8][4];
#pragma unroll
    for (int i = 0; i < 2; i++)
#pragma unroll
        for (int j = 0; j < 8; j++)
#pragma unroll
            for (int k = 0; k < 4; k++) acc[i][j][k] = 0.f;

    const uint32_t a_off = (uint32_t)((wm + (lane & 15)) * SROW + (lane >> 4) * 16);
    const uint32_t w_off = (uint32_t)((wn + (lane & 7) + ((lane >> 4) & 1) * 8) * SROW
                                      + ((lane >> 3) & 1) * 16);

    const int nk = K / 32;
    issue_stage(0, 0); CP_COMMIT();
    if (nk > 1) issue_stage(1, 1);
    CP_COMMIT();

    for (int c = 0; c < nk; ++c) {
        const int s = c & 1;
        CP_WAIT1();
        __syncthreads();

        const uint32_t sAh = sbase + s * STAGE_B;
        const uint32_t sAl = sAh + SBUF;
        const uint32_t sWh = sAh + 2 * SBUF;
        const uint32_t sWl = sAh + 3 * SBUF;

#pragma unroll
        for (int ks = 0; ks < 2; ++ks) {
            const uint32_t ko = ks * 32;
            uint32_t aF[2][4], bF[8][2];
#pragma unroll
            for (int mf = 0; mf < 2; mf++)
                ldsm4(aF[mf][0], aF[mf][1], aF[mf][2], aF[mf][3],
                      sAh + a_off + mf * (16 * SROW) + ko);
#pragma unroll
            for (int p = 0; p < 4; p++) {
                uint32_t r0, r1, r2, r3;
                ldsm4(r0, r1, r2, r3, sWh + w_off + p * (16 * SROW) + ko);
                bF[2*p][0] = r0; bF[2*p][1] = r1;
                bF[2*p+1][0] = r2; bF[2*p+1][1] = r3;
            }
            // pass 1: Ah * Wh
#pragma unroll
            for (int mf = 0; mf < 2; mf++)
#pragma unroll
                for (int nf = 0; nf < 8; nf++)
                    mma16816(acc[mf][nf], aF[mf], bF[nf][0], bF[nf][1]);
            // pass 2: Ah * Wl (transient frags)
#pragma unroll
            for (int p = 0; p < 4; p++) {
                uint32_t c0, c1, c2, c3;
                ldsm4(c0, c1, c2, c3, sWl + w_off + p * (16 * SROW) + ko);
#pragma unroll
                for (int mf = 0; mf < 2; mf++) {
                    mma16816(acc[mf][2*p],   aF[mf], c0, c1);
                    mma16816(acc[mf][2*p+1], aF[mf], c2, c3);
                }
            }
            // pass 3: Al * Wh (transient frags)
#pragma unroll
            for (int mf = 0; mf < 2; mf++) {
                uint32_t e[4];
                ldsm4(e[0], e[1], e[2], e[3],
                      sAl + a_off + mf * (16 * SROW) + ko);
#pragma unroll
                for (int nf = 0; nf < 8; nf++)
                    mma16816(acc[mf][nf], e, bF[nf][0], bF[nf][1]);
            }
        }
        __syncthreads();
        if (c + 2 < nk) issue_stage(c + 2, s);
        CP_COMMIT();
    }

    // epilogue
    const int erow = (lane >> 2);
    const int ecol = (lane & 3) * 2;
#pragma unroll
    for (int nf = 0; nf < 8; nf++) {
        const int col = bn + wn + nf * 8 + ecol;
        const float2 bv = *(const float2*)&bias[col];
#pragma unroll
        for (int mf = 0; mf < 2; mf++) {
            const int r0 = bm + wm + mf * 16 + erow;
            float2 o0, o1;
            o0.x = acc[mf][nf][0] + bv.x; o0.y = acc[mf][nf][1] + bv.y;
            o1.x = acc[mf][nf][2] + bv.x; o1.y = acc[mf][nf][3] + bv.y;
            if (RELU) {
                o0.x = fmaxf(o0.x, 0.f); o0.y = fmaxf(o0.y, 0.f);
                o1.x = fmaxf(o1.x, 0.f); o1.y = fmaxf(o1.y, 0.f);
            }
            if (PAIR) {
                uint32_t h, l;
                split2(o0.x, o0.y, h, l);
                *(uint32_t*)&Ch[(size_t)r0 * N + col] = h;
                *(uint32_t*)&Cl[(size_t)r0 * N + col] = l;
                split2(o1.x, o1.y, h, l);
                *(uint32_t*)&Ch[(size_t)(r0 + 8) * N + col] = h;
                *(uint32_t*)&Cl[(size_t)(r0 + 8) * N + col] = l;
            } else {
                *(float2*)&Cf[(size_t)r0 * N + col] = o0;
                *(float2*)&Cf[(size_t)(r0 + 8) * N + col] = o1;
            }
        }
    }
}

// =================== small SIMT GEMM (head fc2) ===================
__global__ __launch_bounds__(256) void gemm_bias(
    const float* __restrict__ A, const float* __restrict__ W,
    const float* __restrict__ bias, float* __restrict__ C,
    int M, int N, int K)
{
    __shared__ float As[16][68];
    __shared__ float Ws[16][68];
    const int t  = threadIdx.x;
    const int bm = blockIdx.y * 64, bn = blockIdx.x * 64;
    const int tm = (t >> 4) << 2;
    const int tn = (t & 15) << 2;
    const int lr = t >> 2;
    const int lc = (t & 3) << 2;

    float acc[4][4] = {};
    const float* Ap = A + (size_t)(bm + lr) * K + lc;
    const float* Wp = W + (size_t)(bn + lr) * K + lc;

    for (int k0 = 0; k0 < K; k0 += 16) {
        float4 av = *(const float4*)(Ap + k0);
        float4 wv = (bn + lr < N) ? *(const float4*)(Wp + k0) : make_float4(0, 0, 0, 0);
        As[lc+0][lr]=av.x; As[lc+1][lr]=av.y; As[lc+2][lr]=av.z; As[lc+3][lr]=av.w;
        Ws[lc+0][lr]=wv.x; Ws[lc+1][lr]=wv.y; Ws[lc+2][lr]=wv.z; Ws[lc+3][lr]=wv.w;
        __syncthreads();
#pragma unroll
        for (int k = 0; k < 16; k++) {
            float4 a4 = *(const float4*)&As[k][tm];
            float4 w4 = *(const float4*)&Ws[k][tn];
            const float ar[4] = {a4.x, a4.y, a4.z, a4.w};
            const float wr[4] = {w4.x, w4.y, w4.z, w4.w};
#pragma unroll
            for (int r = 0; r < 4; r++)
#pragma unroll
                for (int c = 0; c < 4; c++)
                    acc[r][c] = fmaf(ar[r], wr[c], acc[r][c]);
        }
        __syncthreads();
    }
    if (bn + tn >= N) return;
    float4 bv = *(const float4*)&bias[bn + tn];
    const float bb[4] = {bv.x, bv.y, bv.z, bv.w};
#pragma unroll
    for (int r = 0; r < 4; r++) {
        float4 o; float* op = (float*)&o;
#pragma unroll
        for (int c = 0; c < 4; c++) op[c] = acc[r][c] + bb[c];
        *(float4*)&C[(size_t)(bm + tm + r) * N + bn + tn] = o;
    }
}

// =================== expert select (fp32 in, fp32 + bf16 pair out) ===================
__global__ __launch_bounds__(256) void select_kernel(
    const float* __restrict__ G, const float* __restrict__ A2,
    const int* __restrict__ ST, float* __restrict__ H,
    __nv_bfloat16* __restrict__ Hh, __nv_bfloat16* __restrict__ Hl)
{
    const size_t i = (size_t)blockIdx.x * blockDim.x + threadIdx.x;  // float4 idx
    const int row = (int)(i >> 6);                                   // 64 float4/row
    const float4 v = (ST[row] == 0) ? ((const float4*)G)[i] : ((const float4*)A2)[i];
    ((float4*)H)[i] = v;
    uint2 hi, lo;
    split4(v, hi, lo);
    ((uint2*)Hh)[i] = hi;
    ((uint2*)Hl)[i] = lo;
}

// =================== attention: one warp per (batch, head), bf16-pair out ===========
__global__ __launch_bounds__(256) void attn_kernel(
    const float* __restrict__ QKV,
    __nv_bfloat16* __restrict__ Oh, __nv_bfloat16* __restrict__ Ol)
{
    const int gwarp = (blockIdx.x * blockDim.x + threadIdx.x) >> 5;
    const int lane  = threadIdx.x & 31;
    if (gwarp >= cB * cNH) return;
    const int b = gwarp >> 2, h = gwarp & 3;

    const float* base = QKV + (size_t)b * cS * 768 + h * 64 + 2 * lane;
    float q[cS][2], kk[cS][2], vv[cS][2];
#pragma unroll
    for (int s = 0; s < cS; s++) {
        const float* r = base + s * 768;
        float2 qv = *(const float2*)(r);
        float2 kv = *(const float2*)(r + 256);
        float2 vw = *(const float2*)(r + 512);
        q [s][0] = qv.x; q [s][1] = qv.y;
        kk[s][0] = kv.x; kk[s][1] = kv.y;
        vv[s][0] = vw.x; vv[s][1] = vw.y;
    }
    float sc[cS][cS];
#pragma unroll
    for (int i = 0; i < cS; i++)
#pragma unroll
        for (int j = 0; j < cS; j++) {
            float p = q[i][0] * kk[j][0] + q[i][1] * kk[j][1];
#pragma unroll
            for (int o = 16; o > 0; o >>= 1) p += __shfl_xor_sync(0xFFFFFFFFu, p, o);
            sc[i][j] = p * 0.125f;
        }
#pragma unroll
    for (int i = 0; i < cS; i++) {
        float m = sc[i][0];
#pragma unroll
        for (int j = 1; j < cS; j++) m = fmaxf(m, sc[i][j]);
        float e[cS], s = 0.f;
#pragma unroll
        for (int j = 0; j < cS; j++) { e[j] = expf(sc[i][j] - m); s += e[j]; }
        const float inv = 1.f / s;
        float o0 = 0.f, o1 = 0.f;
#pragma unroll
        for (int j = 0; j < cS; j++) {
            const float a = e[j] * inv;
            o0 = fmaf(a, vv[j][0], o0);
            o1 = fmaf(a, vv[j][1], o1);
        }
        uint32_t hi, lo;
        split2(o0, o1, hi, lo);
        const size_t off = (size_t)(b * cS + i) * cE + h * 64 + 2 * lane;
        *(uint32_t*)&Oh[off] = hi;
        *(uint32_t*)&Ol[off] = lo;
    }
}

// =================== fused residual + layernorm (fp32 + bf16-pair out) ===============
__global__ __launch_bounds__(256) void add_ln_kernel(
    const float* __restrict__ Hin, const float* __restrict__ Cin,
    const float* __restrict__ G, const float* __restrict__ Bv,
    float* __restrict__ Hout,
    __nv_bfloat16* __restrict__ Hh, __nv_bfloat16* __restrict__ Hl)
{
    const int row  = blockIdx.x * 8 + (threadIdx.x >> 5);
    const int lane = threadIdx.x & 31;
    const size_t rb = (size_t)row * cE;

    float2 v[4];
    float s = 0.f;
#pragma unroll
    for (int i = 0; i < 4; i++) {
        const int e = i * 64 + lane * 2;
        float2 a = *(const float2*)&Hin[rb + e];
        float2 b = *(const float2*)&Cin[rb + e];
        v[i].x = a.x + b.x; v[i].y = a.y + b.y;
        s += v[i].x + v[i].y;
    }
#pragma unroll
    for (int o = 16; o > 0; o >>= 1) s += __shfl_xor_sync(0xFFFFFFFFu, s, o);
    const float mean = s * (1.f / cE);

    float vs = 0.f;
#pragma unroll
    for (int i = 0; i < 4; i++) {
        const float dx = v[i].x - mean, dy = v[i].y - mean;
        vs += dx * dx + dy * dy;
    }
#pragma unroll
    for (int o = 16; o > 0; o >>= 1) vs += __shfl_xor_sync(0xFFFFFFFFu, vs, o);
    const float rs = rsqrtf(vs * (1.f / cE) + 1e-5f);

#pragma unroll
    for (int i = 0; i < 4; i++) {
        const int e = i * 64 + lane * 2;
        const float2 g = *(const float2*)&G[e];
        const float2 b = *(const float2*)&Bv[e];
        float2 o;
        o.x = (v[i].x - mean) * rs * g.x + b.x;
        o.y = (v[i].y - mean) * rs * g.y + b.y;
        *(float2*)&Hout[rb + e] = o;
        uint32_t hi, lo;
        split2(o.x, o.y, hi, lo);
        *(uint32_t*)&Hh[rb + e] = hi;
        *(uint32_t*)&Hl[rb + e] = lo;
    }
}

// =================== final tiny projection ===================
__global__ __launch_bounds__(256) void out_kernel(
    const float* __restrict__ Z, const float* __restrict__ OW,
    const float* __restrict__ OB, float* __restrict__ OUT)
{
    const int b = blockIdx.x * blockDim.x + threadIdx.x;
    if (b >= cB) return;
    float acc[cC];
#pragma unroll
    for (int c = 0; c < cC; c++) acc[c] = OB[c];
    const float* zr = Z + (size_t)b * 64;
    for (int k = 0; k < 64; k++) {
        const float z = zr[k];
#pragma unroll
        for (int c = 0; c < cC; c++) acc[c] = fmaf(z, OW[c * 64 + k], acc[c]);
    }
#pragma unroll
    for (int c = 0; c < cC; c++) OUT[(size_t)b * cC + c] = acc[c];
}

// ---------------- launch ----------------
template<typename T>
static T* symaddr(const void* sym) {
    void* p = nullptr;
    cudaGetSymbolAddress(&p, sym);
    return (T*)p;
}
static void conv(const float* src, __nv_bfloat16* h, __nv_bfloat16* l, size_t n) {
    const size_t n4 = n / 4;
    convert_split<<<(unsigned)((n4 + 255) / 256), 256>>>(src, h, l, n4);
}

extern "C" void kernel_launch(void* const* d_in, const int* in_sizes, int n_in,
                              void* d_out, int out_size)
{
    const float* x       = (const float*)d_in[0];
    const int*   st      = (const int*)  d_in[1];
    const float* gps_w   = (const float*)d_in[2];
    const float* gps_b   = (const float*)d_in[3];
    const float* ang_w   = (const float*)d_in[4];
    const float* ang_b   = (const float*)d_in[5];
    const float* qkv_w   = (const float*)d_in[6];
    const float* qkv_b   = (const float*)d_in[7];
    const float* attn_ow = (const float*)d_in[8];
    const float* attn_ob = (const float*)d_in[9];
    const float* ln1_g   = (const float*)d_in[10];
    const float* ln1_b   = (const float*)d_in[11];
    const float* ff1_w   = (const float*)d_in[12];
    const float* ff1_b   = (const float*)d_in[13];
    const float* ff2_w   = (const float*)d_in[14];
    const float* ff2_b   = (const float*)d_in[15];
    const float* ln2_g   = (const float*)d_in[16];
    const float* ln2_b   = (const float*)d_in[17];
    const float* fc1_w   = (const float*)d_in[18];
    const float* fc1_b   = (const float*)d_in[19];
    const float* fc2_w   = (const float*)d_in[20];
    const float* fc2_b   = (const float*)d_in[21];
    const float* out_w   = (const float*)d_in[22];
    const float* out_b   = (const float*)d_in[23];
    float* out = (float*)d_out;

    float* H  = symaddr<float>(g_H);
    float* T  = symaddr<float>(g_T);
    float* Cb = symaddr<float>(g_Cb);
    float* Z1 = symaddr<float>(g_Z1);
    float* Z2 = symaddr<float>(g_Z2);
    __nv_bfloat16* Xh = symaddr<__nv_bfloat16>(g_Xh);
    __nv_bfloat16* Xl = symaddr<__nv_bfloat16>(g_Xl);
    __nv_bfloat16* Hh = symaddr<__nv_bfloat16>(g_Hh);
    __nv_bfloat16* Hl = symaddr<__nv_bfloat16>(g_Hl);
    __nv_bfloat16* Oh = symaddr<__nv_bfloat16>(g_Oh);
    __nv_bfloat16* Ol = symaddr<__nv_bfloat16>(g_Ol);
    __nv_bfloat16* Th = symaddr<__nv_bfloat16>(g_Th);
    __nv_bfloat16* Tl = symaddr<__nv_bfloat16>(g_Tl);
    __nv_bfloat16* Wh = symaddr<__nv_bfloat16>(g_Wh);
    __nv_bfloat16* Wl = symaddr<__nv_bfloat16>(g_Wl);

    static bool attr_set = false;
    if (!attr_set) {
        cudaFuncSetAttribute((const void*)gemm_mma<false,false>,
                             cudaFuncAttributeMaxDynamicSharedMemorySize, GEMM_SMEM);
        cudaFuncSetAttribute((const void*)gemm_mma<true,false>,
                             cudaFuncAttributeMaxDynamicSharedMemorySize, GEMM_SMEM);
        cudaFuncSetAttribute((const void*)gemm_mma<true,true>,
                             cudaFuncAttributeMaxDynamicSharedMemorySize, GEMM_SMEM);
        attr_set = true;
    }

    // 0. convert inputs + weights to bf16 hi/lo
    conv(x, Xh, Xl, (size_t)cBS * cD);
    conv(gps_w,   Wh + OFF_GPS, Wl + OFF_GPS, 131072);
    conv(ang_w,   Wh + OFF_ANG, Wl + OFF_ANG, 131072);
    conv(qkv_w,   Wh + OFF_QKV, Wl + OFF_QKV, 393216);
    conv(attn_ow, Wh + OFF_OW,  Wl + OFF_OW,  131072);
    conv(ff1_w,   Wh + OFF_FF1, Wl + OFF_FF1, 1048576);
    conv(ff2_w,   Wh + OFF_FF2, Wl + OFF_FF2, 1048576);
    conv(fc1_w,   Wh + OFF_FC1, Wl + OFF_FC1, 163840);

    const int MT = cBS / 128;   // 1280 row tiles
    float* G  = T;                      // expert outputs (fp32 scratch)
    float* A2 = T + (size_t)cBS * cE;   // fits in g_T ([BS,768])

    // 1. dual-expert embed + select
    gemm_mma<true,false><<<dim3(cE/128, MT), 256, GEMM_SMEM>>>(
        Xh, Xl, Wh + OFF_GPS, Wl + OFF_GPS, gps_b, G, nullptr, nullptr, cBS, cE, cD);
    gemm_mma<true,false><<<dim3(cE/128, MT), 256, GEMM_SMEM>>>(
        Xh, Xl, Wh + OFF_ANG, Wl + OFF_ANG, ang_b, A2, nullptr, nullptr, cBS, cE, cD);
    select_kernel<<<(cBS * cE / 4) / 256, 256>>>(G, A2, st, H, Hh, Hl);

    // 2. transformer layers
    for (int l = 0; l < cL; l++) {
        const __nv_bfloat16* qwh = Wh + OFF_QKV + (size_t)l * 768 * cE;
        const __nv_bfloat16* qwl = Wl + OFF_QKV + (size_t)l * 768 * cE;
        const __nv_bfloat16* owh = Wh + OFF_OW  + (size_t)l * cE * cE;
        const __nv_bfloat16* owl = Wl + OFF_OW  + (size_t)l * cE * cE;
        const __nv_bfloat16* f1h = Wh + OFF_FF1 + (size_t)l * cF * cE;
        const __nv_bfloat16* f1l = Wl + OFF_FF1 + (size_t)l * cF * cE;
        const __nv_bfloat16* f2h = Wh + OFF_FF2 + (size_t)l * cE * cF;
        const __nv_bfloat16* f2l = Wl + OFF_FF2 + (size_t)l * cE * cF;
        const float* qb  = qkv_b   + (size_t)l * 3 * cE;
        const float* ob  = attn_ob + (size_t)l * cE;
        const float* f1b = ff1_b   + (size_t)l * cF;
        const float* f2b = ff2_b   + (size_t)l * cE;

        gemm_mma<false,false><<<dim3(768/128, MT), 256, GEMM_SMEM>>>(
            Hh, Hl, qwh, qwl, qb, T, nullptr, nullptr, cBS, 768, cE);
        attn_kernel<<<(cB * cNH * 32) / 256, 256>>>(T, Oh, Ol);
        gemm_mma<false,false><<<dim3(cE/128, MT), 256, GEMM_SMEM>>>(
            Oh, Ol, owh, owl, ob, Cb, nullptr, nullptr, cBS, cE, cE);
        add_ln_kernel<<<cBS / 8, 256>>>(H, Cb, ln1_g + l * cE, ln1_b + l * cE, H, Hh, Hl);
        gemm_mma<true,true><<<dim3(cF/128, MT), 256, GEMM_SMEM>>>(
            Hh, Hl, f1h, f1l, f1b, nullptr, Th, Tl, cBS, cF, cE);
        gemm_mma<false,false><<<dim3(cE/128, MT), 256, GEMM_SMEM>>>(
            Th, Tl, f2h, f2l, f2b, Cb, nullptr, nullptr, cBS, cE, cF);
        add_ln_kernel<<<cBS / 8, 256>>>(H, Cb, ln2_g + l * cE, ln2_b + l * cE, H, Hh, Hl);
    }

    // 3. head: Hh/Hl viewed as [B,1280]
    gemm_mma<false,false><<<dim3(1, cB/128), 256, GEMM_SMEM>>>(
        Hh, Hl, Wh + OFF_FC1, Wl + OFF_FC1, fc1_b, Z1, nullptr, nullptr, cB, 128, cZK);
    gemm_bias<<<dim3(1, cB/64), 256>>>(Z1, fc2_w, fc2_b, Z2, cB, 64, 128);
    out_kernel<<<cB / 256, 256>>>(Z2, out_w, out_b, out);
}

// round 10
// speedup vs baseline: 1.5349x; 1.3859x over previous
#include <cuda_runtime.h>
#include <cuda_fp16.h>
#include <cstdint>

// ---------------- problem constants ----------------
constexpr int cB = 32768, cS = 5, cD = 512, cE = 256, cNH = 4,
              cF = 2048, cL = 2, cC = 5;
constexpr int cBS = cB * cS;               // 163840 rows
constexpr int cZK = cS * cE;               // 1280, head input dim

// ---------------- scratch (device globals; no allocs) ----------------
__device__ __align__(16) float g_H [(size_t)cBS * cE];    // residual stream fp32
__device__ __align__(16) float g_T [(size_t)cBS * 768];   // qkv fp32
__device__ __align__(16) float g_Cb[(size_t)cBS * cE];    // pre-LN gemm out fp32
__device__ __align__(16) float g_Z1[(size_t)cB * 128];
__device__ __align__(16) float g_Z2[(size_t)cB * 64];

__device__ __align__(16) __half g_Xh[(size_t)cBS * cD];
__device__ __align__(16) __half g_Xl[(size_t)cBS * cD];
__device__ __align__(16) __half g_Hh[(size_t)cBS * cE];
__device__ __align__(16) __half g_Hl[(size_t)cBS * cE];
__device__ __align__(16) __half g_Oh[(size_t)cBS * cE];
__device__ __align__(16) __half g_Ol[(size_t)cBS * cE];
__device__ __align__(16) __half g_Th[(size_t)cBS * cF];
__device__ __align__(16) __half g_Tl[(size_t)cBS * cF];

// weight fp16 pool (element offsets)
constexpr size_t OFF_GPS = 0;                       // 256*512
constexpr size_t OFF_ANG = OFF_GPS + 131072;
constexpr size_t OFF_QKV = OFF_ANG + 131072;        // L*768*256
constexpr size_t OFF_OW  = OFF_QKV + 393216;        // L*256*256
constexpr size_t OFF_FF1 = OFF_OW  + 131072;        // L*2048*256
constexpr size_t OFF_FF2 = OFF_FF1 + 1048576;       // L*256*2048
constexpr size_t OFF_FC1 = OFF_FF2 + 1048576;       // 128*1280
constexpr size_t W_TOTAL = OFF_FC1 + 163840;
__device__ __align__(16) __half g_W[W_TOTAL];

// =================== helpers ===================
__device__ __forceinline__ uint32_t smem_u32(const void* p) {
    uint32_t a;
    asm("{ .reg .u64 t; cvta.to.shared.u64 t, %1; cvt.u32.u64 %0, t; }"
        : "=r"(a) : "l"(p));
    return a;
}
__device__ __forceinline__ void ldsm4(uint32_t& r0, uint32_t& r1,
                                      uint32_t& r2, uint32_t& r3, uint32_t addr) {
    asm volatile("ldmatrix.sync.aligned.m8n8.x4.shared.b16 {%0,%1,%2,%3}, [%4];"
                 : "=r"(r0), "=r"(r1), "=r"(r2), "=r"(r3) : "r"(addr));
}
__device__ __forceinline__ void mma16816h(float* d, const uint32_t* a,
                                          uint32_t b0, uint32_t b1) {
    asm volatile(
        "mma.sync.aligned.m16n8k16.row.col.f32.f16.f16.f32 "
        "{%0,%1,%2,%3}, {%4,%5,%6,%7}, {%8,%9}, {%0,%1,%2,%3};"
        : "+f"(d[0]), "+f"(d[1]), "+f"(d[2]), "+f"(d[3])
        : "r"(a[0]), "r"(a[1]), "r"(a[2]), "r"(a[3]), "r"(b0), "r"(b1));
}
__device__ __forceinline__ void cpasync16(uint32_t dst, const void* src) {
    asm volatile("cp.async.cg.shared.global [%0], [%1], 16;" :: "r"(dst), "l"(src));
}
#define CP_COMMIT() asm volatile("cp.async.commit_group;" ::: "memory")
#define CP_WAIT1()  asm volatile("cp.async.wait_group 1;" ::: "memory")

// split float2 -> hi half2 (as u32) and lo half2 (as u32)
__device__ __forceinline__ void split2h(float x, float y, uint32_t& hi, uint32_t& lo) {
    __half2 h = __float22half2_rn(make_float2(x, y));
    float2 hf = __half22float2(h);
    __half2 l = __float22half2_rn(make_float2(x - hf.x, y - hf.y));
    hi = *(uint32_t*)&h;
    lo = *(uint32_t*)&l;
}
__device__ __forceinline__ void split4h(float4 v, uint2& hi, uint2& lo) {
    uint32_t h0, l0, h1, l1;
    split2h(v.x, v.y, h0, l0);
    split2h(v.z, v.w, h1, l1);
    hi = make_uint2(h0, h1);
    lo = make_uint2(l0, l1);
}

// =================== fp32 -> fp16 converters ===================
__global__ __launch_bounds__(256) void convert_split(
    const float* __restrict__ src, __half* __restrict__ h,
    __half* __restrict__ l, size_t n4)
{
    const size_t i = (size_t)blockIdx.x * blockDim.x + threadIdx.x;
    if (i >= n4) return;
    uint2 hi, lo;
    split4h(((const float4*)src)[i], hi, lo);
    ((uint2*)h)[i] = hi;
    ((uint2*)l)[i] = lo;
}
__global__ __launch_bounds__(256) void convert_h(
    const float* __restrict__ src, __half* __restrict__ dst, size_t n4)
{
    const size_t i = (size_t)blockIdx.x * blockDim.x + threadIdx.x;
    if (i >= n4) return;
    float4 v = ((const float4*)src)[i];
    __half2 h0 = __float22half2_rn(make_float2(v.x, v.y));
    __half2 h1 = __float22half2_rn(make_float2(v.z, v.w));
    ((uint2*)dst)[i] = make_uint2(*(uint32_t*)&h0, *(uint32_t*)&h1);
}

// =================== tensor-core GEMM: CTA 128x128, warp tile 32x64 ================
// 8 warps as 4(M) x 2(N). 2-pass fp16: C = (Ah+Al).W^T + bias.
// M%128==0, N%128==0, K%32==0.
constexpr int SROW = 80;                   // smem row stride (bytes)
constexpr int SBUF = 128 * SROW;           // 10240 B per operand
constexpr int STAGE_B = 3 * SBUF;          // 30720 B per stage (Ah,Al,W)
constexpr int GEMM_SMEM = 2 * STAGE_B;     // 61440 B

template<bool RELU, bool PAIR>
__global__ __launch_bounds__(256, 2) void gemm_mma(
    const __half* __restrict__ Ah, const __half* __restrict__ Al,
    const __half* __restrict__ W,
    const float* __restrict__ bias,
    float* __restrict__ Cf,
    __half* __restrict__ Ch, __half* __restrict__ Cl,
    int M, int N, int K)
{
    extern __shared__ char sm[];
    const uint32_t sbase = smem_u32(sm);

    const int tid = threadIdx.x;
    const int wid = tid >> 5, lane = tid & 31;
    const int bm = blockIdx.y * 128, bn = blockIdx.x * 128;
    const int wm = (wid >> 1) * 32, wn = (wid & 1) * 64;

    // loader: thread -> row tid/2 (0..127), 16B chunks q0, q0+1 where q0=(tid&1)*2
    const int lrow = tid >> 1;
    const int q0 = (tid & 1) * 2;
    const __half* pAh = Ah + (size_t)(bm + lrow) * K + q0 * 8;
    const __half* pAl = Al + (size_t)(bm + lrow) * K + q0 * 8;
    const __half* pW  = W  + (size_t)(bn + lrow) * K + q0 * 8;
    const uint32_t soff = (uint32_t)(lrow * SROW + q0 * 16);

    auto issue_stage = [&](int c, int s) {
        const uint32_t st = sbase + s * STAGE_B + soff;
        const size_t ko = (size_t)c * 32;
        cpasync16(st,                pAh + ko);
        cpasync16(st + 16,           pAh + ko + 8);
        cpasync16(st + SBUF,         pAl + ko);
        cpasync16(st + SBUF + 16,    pAl + ko + 8);
        cpasync16(st + 2*SBUF,       pW + ko);
        cpasync16(st + 2*SBUF + 16,  pW + ko + 8);
    };

    float acc[2][8][4];
#pragma unroll
    for (int i = 0; i < 2; i++)
#pragma unroll
        for (int j = 0; j < 8; j++)
#pragma unroll
            for (int k = 0; k < 4; k++) acc[i][j][k] = 0.f;

    const uint32_t a_off = (uint32_t)((wm + (lane & 15)) * SROW + (lane >> 4) * 16);
    const uint32_t w_off = (uint32_t)((wn + (lane & 7) + ((lane >> 4) & 1) * 8) * SROW
                                      + ((lane >> 3) & 1) * 16);

    const int nk = K / 32;
    issue_stage(0, 0); CP_COMMIT();
    if (nk > 1) issue_stage(1, 1);
    CP_COMMIT();

    for (int c = 0; c < nk; ++c) {
        const int s = c & 1;
        CP_WAIT1();
        __syncthreads();

        const uint32_t sAh = sbase + s * STAGE_B;
        const uint32_t sAl = sAh + SBUF;
        const uint32_t sW  = sAh + 2 * SBUF;

#pragma unroll
        for (int ks = 0; ks < 2; ++ks) {
            const uint32_t ko = ks * 32;
            uint32_t aF[2][4], bF[8][2];
#pragma unroll
            for (int mf = 0; mf < 2; mf++)
                ldsm4(aF[mf][0], aF[mf][1], aF[mf][2], aF[mf][3],
                      sAh + a_off + mf * (16 * SROW) + ko);
#pragma unroll
            for (int p = 0; p < 4; p++) {
                uint32_t r0, r1, r2, r3;
                ldsm4(r0, r1, r2, r3, sW + w_off + p * (16 * SROW) + ko);
                bF[2*p][0] = r0; bF[2*p][1] = r1;
                bF[2*p+1][0] = r2; bF[2*p+1][1] = r3;
            }
            // pass 1: Ah * W
#pragma unroll
            for (int mf = 0; mf < 2; mf++)
#pragma unroll
                for (int nf = 0; nf < 8; nf++)
                    mma16816h(acc[mf][nf], aF[mf], bF[nf][0], bF[nf][1]);
            // pass 2: Al * W (transient frags)
#pragma unroll
            for (int mf = 0; mf < 2; mf++) {
                uint32_t e[4];
                ldsm4(e[0], e[1], e[2], e[3],
                      sAl + a_off + mf * (16 * SROW) + ko);
#pragma unroll
                for (int nf = 0; nf < 8; nf++)
                    mma16816h(acc[mf][nf], e, bF[nf][0], bF[nf][1]);
            }
        }
        __syncthreads();
        if (c + 2 < nk) issue_stage(c + 2, s);
        CP_COMMIT();
    }

    // epilogue
    const int erow = (lane >> 2);
    const int ecol = (lane & 3) * 2;
#pragma unroll
    for (int nf = 0; nf < 8; nf++) {
        const int col = bn + wn + nf * 8 + ecol;
        const float2 bv = *(const float2*)&bias[col];
#pragma unroll
        for (int mf = 0; mf < 2; mf++) {
            const int r0 = bm + wm + mf * 16 + erow;
            float2 o0, o1;
            o0.x = acc[mf][nf][0] + bv.x; o0.y = acc[mf][nf][1] + bv.y;
            o1.x = acc[mf][nf][2] + bv.x; o1.y = acc[mf][nf][3] + bv.y;
            if (RELU) {
                o0.x = fmaxf(o0.x, 0.f); o0.y = fmaxf(o0.y, 0.f);
                o1.x = fmaxf(o1.x, 0.f); o1.y = fmaxf(o1.y, 0.f);
            }
            if (PAIR) {
                uint32_t h, l;
                split2h(o0.x, o0.y, h, l);
                *(uint32_t*)&Ch[(size_t)r0 * N + col] = h;
                *(uint32_t*)&Cl[(size_t)r0 * N + col] = l;
                split2h(o1.x, o1.y, h, l);
                *(uint32_t*)&Ch[(size_t)(r0 + 8) * N + col] = h;
                *(uint32_t*)&Cl[(size_t)(r0 + 8) * N + col] = l;
            } else {
                *(float2*)&Cf[(size_t)r0 * N + col] = o0;
                *(float2*)&Cf[(size_t)(r0 + 8) * N + col] = o1;
            }
        }
    }
}

// =================== small SIMT GEMM (head fc2) ===================
__global__ __launch_bounds__(256) void gemm_bias(
    const float* __restrict__ A, const float* __restrict__ W,
    const float* __restrict__ bias, float* __restrict__ C,
    int M, int N, int K)
{
    __shared__ float As[16][68];
    __shared__ float Ws[16][68];
    const int t  = threadIdx.x;
    const int bm = blockIdx.y * 64, bn = blockIdx.x * 64;
    const int tm = (t >> 4) << 2;
    const int tn = (t & 15) << 2;
    const int lr = t >> 2;
    const int lc = (t & 3) << 2;

    float acc[4][4] = {};
    const float* Ap = A + (size_t)(bm + lr) * K + lc;
    const float* Wp = W + (size_t)(bn + lr) * K + lc;

    for (int k0 = 0; k0 < K; k0 += 16) {
        float4 av = *(const float4*)(Ap + k0);
        float4 wv = (bn + lr < N) ? *(const float4*)(Wp + k0) : make_float4(0, 0, 0, 0);
        As[lc+0][lr]=av.x; As[lc+1][lr]=av.y; As[lc+2][lr]=av.z; As[lc+3][lr]=av.w;
        Ws[lc+0][lr]=wv.x; Ws[lc+1][lr]=wv.y; Ws[lc+2][lr]=wv.z; Ws[lc+3][lr]=wv.w;
        __syncthreads();
#pragma unroll
        for (int k = 0; k < 16; k++) {
            float4 a4 = *(const float4*)&As[k][tm];
            float4 w4 = *(const float4*)&Ws[k][tn];
            const float ar[4] = {a4.x, a4.y, a4.z, a4.w};
            const float wr[4] = {w4.x, w4.y, w4.z, w4.w};
#pragma unroll
            for (int r = 0; r < 4; r++)
#pragma unroll
                for (int c = 0; c < 4; c++)
                    acc[r][c] = fmaf(ar[r], wr[c], acc[r][c]);
        }
        __syncthreads();
    }
    if (bn + tn >= N) return;
    float4 bv = *(const float4*)&bias[bn + tn];
    const float bb[4] = {bv.x, bv.y, bv.z, bv.w};
#pragma unroll
    for (int r = 0; r < 4; r++) {
        float4 o; float* op = (float*)&o;
#pragma unroll
        for (int c = 0; c < 4; c++) op[c] = acc[r][c] + bb[c];
        *(float4*)&C[(size_t)(bm + tm + r) * N + bn + tn] = o;
    }
}

// =================== expert select (fp32 in, fp32 + fp16 pair out) ===================
__global__ __launch_bounds__(256) void select_kernel(
    const float* __restrict__ G, const float* __restrict__ A2,
    const int* __restrict__ ST, float* __restrict__ H,
    __half* __restrict__ Hh, __half* __restrict__ Hl)
{
    const size_t i = (size_t)blockIdx.x * blockDim.x + threadIdx.x;  // float4 idx
    const int row = (int)(i >> 6);                                   // 64 float4/row
    const float4 v = (ST[row] == 0) ? ((const float4*)G)[i] : ((const float4*)A2)[i];
    ((float4*)H)[i] = v;
    uint2 hi, lo;
    split4h(v, hi, lo);
    ((uint2*)Hh)[i] = hi;
    ((uint2*)Hl)[i] = lo;
}

// =================== attention: one warp per (batch, head), fp16-pair out ===========
__global__ __launch_bounds__(256) void attn_kernel(
    const float* __restrict__ QKV,
    __half* __restrict__ Oh, __half* __restrict__ Ol)
{
    const int gwarp = (blockIdx.x * blockDim.x + threadIdx.x) >> 5;
    const int lane  = threadIdx.x & 31;
    if (gwarp >= cB * cNH) return;
    const int b = gwarp >> 2, h = gwarp & 3;

    const float* base = QKV + (size_t)b * cS * 768 + h * 64 + 2 * lane;
    float q[cS][2], kk[cS][2], vv[cS][2];
#pragma unroll
    for (int s = 0; s < cS; s++) {
        const float* r = base + s * 768;
        float2 qv = *(const float2*)(r);
        float2 kv = *(const float2*)(r + 256);
        float2 vw = *(const float2*)(r + 512);
        q [s][0] = qv.x; q [s][1] = qv.y;
        kk[s][0] = kv.x; kk[s][1] = kv.y;
        vv[s][0] = vw.x; vv[s][1] = vw.y;
    }
    float sc[cS][cS];
#pragma unroll
    for (int i = 0; i < cS; i++)
#pragma unroll
        for (int j = 0; j < cS; j++) {
            float p = q[i][0] * kk[j][0] + q[i][1] * kk[j][1];
#pragma unroll
            for (int o = 16; o > 0; o >>= 1) p += __shfl_xor_sync(0xFFFFFFFFu, p, o);
            sc[i][j] = p * 0.125f;
        }
#pragma unroll
    for (int i = 0; i < cS; i++) {
        float m = sc[i][0];
#pragma unroll
        for (int j = 1; j < cS; j++) m = fmaxf(m, sc[i][j]);
        float e[cS], s = 0.f;
#pragma unroll
        for (int j = 0; j < cS; j++) { e[j] = expf(sc[i][j] - m); s += e[j]; }
        const float inv = 1.f / s;
        float o0 = 0.f, o1 = 0.f;
#pragma unroll
        for (int j = 0; j < cS; j++) {
            const float a = e[j] * inv;
            o0 = fmaf(a, vv[j][0], o0);
            o1 = fmaf(a, vv[j][1], o1);
        }
        uint32_t hi, lo;
        split2h(o0, o1, hi, lo);
        const size_t off = (size_t)(b * cS + i) * cE + h * 64 + 2 * lane;
        *(uint32_t*)&Oh[off] = hi;
        *(uint32_t*)&Ol[off] = lo;
    }
}

// =================== fused residual + layernorm (fp32 + fp16-pair out) ===============
__global__ __launch_bounds__(256) void add_ln_kernel(
    const float* __restrict__ Hin, const float* __restrict__ Cin,
    const float* __restrict__ G, const float* __restrict__ Bv,
    float* __restrict__ Hout,
    __half* __restrict__ Hh, __half* __restrict__ Hl)
{
    const int row  = blockIdx.x * 8 + (threadIdx.x >> 5);
    const int lane = threadIdx.x & 31;
    const size_t rb = (size_t)row * cE;

    float2 v[4];
    float s = 0.f;
#pragma unroll
    for (int i = 0; i < 4; i++) {
        const int e = i * 64 + lane * 2;
        float2 a = *(const float2*)&Hin[rb + e];
        float2 b = *(const float2*)&Cin[rb + e];
        v[i].x = a.x + b.x; v[i].y = a.y + b.y;
        s += v[i].x + v[i].y;
    }
#pragma unroll
    for (int o = 16; o > 0; o >>= 1) s += __shfl_xor_sync(0xFFFFFFFFu, s, o);
    const float mean = s * (1.f / cE);

    float vs = 0.f;
#pragma unroll
    for (int i = 0; i < 4; i++) {
        const float dx = v[i].x - mean, dy = v[i].y - mean;
        vs += dx * dx + dy * dy;
    }
#pragma unroll
    for (int o = 16; o > 0; o >>= 1) vs += __shfl_xor_sync(0xFFFFFFFFu, vs, o);
    const float rs = rsqrtf(vs * (1.f / cE) + 1e-5f);

#pragma unroll
    for (int i = 0; i < 4; i++) {
        const int e = i * 64 + lane * 2;
        const float2 g = *(const float2*)&G[e];
        const float2 b = *(const float2*)&Bv[e];
        float2 o;
        o.x = (v[i].x - mean) * rs * g.x + b.x;
        o.y = (v[i].y - mean) * rs * g.y + b.y;
        *(float2*)&Hout[rb + e] = o;
        uint32_t hi, lo;
        split2h(o.x, o.y, hi, lo);
        *(uint32_t*)&Hh[rb + e] = hi;
        *(uint32_t*)&Hl[rb + e] = lo;
    }
}

// =================== final tiny projection ===================
__global__ __launch_bounds__(256) void out_kernel(
    const float* __restrict__ Z, const float* __restrict__ OW,
    const float* __restrict__ OB, float* __restrict__ OUT)
{
    const int b = blockIdx.x * blockDim.x + threadIdx.x;
    if (b >= cB) return;
    float acc[cC];
#pragma unroll
    for (int c = 0; c < cC; c++) acc[c] = OB[c];
    const float* zr = Z + (size_t)b * 64;
    for (int k = 0; k < 64; k++) {
        const float z = zr[k];
#pragma unroll
        for (int c = 0; c < cC; c++) acc[c] = fmaf(z, OW[c * 64 + k], acc[c]);
    }
#pragma unroll
    for (int c = 0; c < cC; c++) OUT[(size_t)b * cC + c] = acc[c];
}

// ---------------- launch ----------------
template<typename T>
static T* symaddr(const void* sym) {
    void* p = nullptr;
    cudaGetSymbolAddress(&p, sym);
    return (T*)p;
}
static void conv_pair(const float* src, __half* h, __half* l, size_t n) {
    const size_t n4 = n / 4;
    convert_split<<<(unsigned)((n4 + 255) / 256), 256>>>(src, h, l, n4);
}
static void conv_w(const float* src, __half* dst, size_t n) {
    const size_t n4 = n / 4;
    convert_h<<<(unsigned)((n4 + 255) / 256), 256>>>(src, dst, n4);
}

extern "C" void kernel_launch(void* const* d_in, const int* in_sizes, int n_in,
                              void* d_out, int out_size)
{
    const float* x       = (const float*)d_in[0];
    const int*   st      = (const int*)  d_in[1];
    const float* gps_w   = (const float*)d_in[2];
    const float* gps_b   = (const float*)d_in[3];
    const float* ang_w   = (const float*)d_in[4];
    const float* ang_b   = (const float*)d_in[5];
    const float* qkv_w   = (const float*)d_in[6];
    const float* qkv_b   = (const float*)d_in[7];
    const float* attn_ow = (const float*)d_in[8];
    const float* attn_ob = (const float*)d_in[9];
    const float* ln1_g   = (const float*)d_in[10];
    const float* ln1_b   = (const float*)d_in[11];
    const float* ff1_w   = (const float*)d_in[12];
    const float* ff1_b   = (const float*)d_in[13];
    const float* ff2_w   = (const float*)d_in[14];
    const float* ff2_b   = (const float*)d_in[15];
    const float* ln2_g   = (const float*)d_in[16];
    const float* ln2_b   = (const float*)d_in[17];
    const float* fc1_w   = (const float*)d_in[18];
    const float* fc1_b   = (const float*)d_in[19];
    const float* fc2_w   = (const float*)d_in[20];
    const float* fc2_b   = (const float*)d_in[21];
    const float* out_w   = (const float*)d_in[22];
    const float* out_b   = (const float*)d_in[23];
    float* out = (float*)d_out;

    float* H  = symaddr<float>(g_H);
    float* T  = symaddr<float>(g_T);
    float* Cb = symaddr<float>(g_Cb);
    float* Z1 = symaddr<float>(g_Z1);
    float* Z2 = symaddr<float>(g_Z2);
    __half* Xh = symaddr<__half>(g_Xh);
    __half* Xl = symaddr<__half>(g_Xl);
    __half* Hh = symaddr<__half>(g_Hh);
    __half* Hl = symaddr<__half>(g_Hl);
    __half* Oh = symaddr<__half>(g_Oh);
    __half* Ol = symaddr<__half>(g_Ol);
    __half* Th = symaddr<__half>(g_Th);
    __half* Tl = symaddr<__half>(g_Tl);
    __half* W  = symaddr<__half>(g_W);

    static bool attr_set = false;
    if (!attr_set) {
        cudaFuncSetAttribute((const void*)gemm_mma<false,false>,
                             cudaFuncAttributeMaxDynamicSharedMemorySize, GEMM_SMEM);
        cudaFuncSetAttribute((const void*)gemm_mma<true,false>,
                             cudaFuncAttributeMaxDynamicSharedMemorySize, GEMM_SMEM);
        cudaFuncSetAttribute((const void*)gemm_mma<true,true>,
                             cudaFuncAttributeMaxDynamicSharedMemorySize, GEMM_SMEM);
        attr_set = true;
    }

    // 0. convert input (pair) + weights (single fp16)
    conv_pair(x, Xh, Xl, (size_t)cBS * cD);
    conv_w(gps_w,   W + OFF_GPS, 131072);
    conv_w(ang_w,   W + OFF_ANG, 131072);
    conv_w(qkv_w,   W + OFF_QKV, 393216);
    conv_w(attn_ow, W + OFF_OW,  131072);
    conv_w(ff1_w,   W + OFF_FF1, 1048576);
    conv_w(ff2_w,   W + OFF_FF2, 1048576);
    conv_w(fc1_w,   W + OFF_FC1, 163840);

    const int MT = cBS / 128;   // 1280 row tiles
    float* G  = T;                      // expert outputs (fp32 scratch)
    float* A2 = T + (size_t)cBS * cE;   // fits in g_T ([BS,768])

    // 1. dual-expert embed + select
    gemm_mma<true,false><<<dim3(cE/128, MT), 256, GEMM_SMEM>>>(
        Xh, Xl, W + OFF_GPS, gps_b, G, nullptr, nullptr, cBS, cE, cD);
    gemm_mma<true,false><<<dim3(cE/128, MT), 256, GEMM_SMEM>>>(
        Xh, Xl, W + OFF_ANG, ang_b, A2, nullptr, nullptr, cBS, cE, cD);
    select_kernel<<<(cBS * cE / 4) / 256, 256>>>(G, A2, st, H, Hh, Hl);

    // 2. transformer layers
    for (int l = 0; l < cL; l++) {
        const __half* qw  = W + OFF_QKV + (size_t)l * 768 * cE;
        const __half* ow  = W + OFF_OW  + (size_t)l * cE * cE;
        const __half* f1w = W + OFF_FF1 + (size_t)l * cF * cE;
        const __half* f2w = W + OFF_FF2 + (size_t)l * cE * cF;
        const float* qb  = qkv_b   + (size_t)l * 3 * cE;
        const float* ob  = attn_ob + (size_t)l * cE;
        const float* f1b = ff1_b   + (size_t)l * cF;
        const float* f2b = ff2_b   + (size_t)l * cE;

        gemm_mma<false,false><<<dim3(768/128, MT), 256, GEMM_SMEM>>>(
            Hh, Hl, qw, qb, T, nullptr, nullptr, cBS, 768, cE);
        attn_kernel<<<(cB * cNH * 32) / 256, 256>>>(T, Oh, Ol);
        gemm_mma<false,false><<<dim3(cE/128, MT), 256, GEMM_SMEM>>>(
            Oh, Ol, ow, ob, Cb, nullptr, nullptr, cBS, cE, cE);
        add_ln_kernel<<<cBS / 8, 256>>>(H, Cb, ln1_g + l * cE, ln1_b + l * cE, H, Hh, Hl);
        gemm_mma<true,true><<<dim3(cF/128, MT), 256, GEMM_SMEM>>>(
            Hh, Hl, f1w, f1b, nullptr, Th, Tl, cBS, cF, cE);
        gemm_mma<false,false><<<dim3(cE/128, MT), 256, GEMM_SMEM>>>(
            Th, Tl, f2w, f2b, Cb, nullptr, nullptr, cBS, cE, cF);
        add_ln_kernel<<<cBS / 8, 256>>>(H, Cb, ln2_g + l * cE, ln2_b + l * cE, H, Hh, Hl);
    }

    // 3. head: Hh/Hl viewed as [B,1280]
    gemm_mma<false,false><<<dim3(1, cB/128), 256, GEMM_SMEM>>>(
        Hh, Hl, W + OFF_FC1, fc1_b, Z1, nullptr, nullptr, cB, 128, cZK);
    gemm_bias<<<dim3(1, cB/64), 256>>>(Z1, fc2_w, fc2_b, Z2, cB, 64, 128);
    out_kernel<<<cB / 256, 256>>>(Z2, out_w, out_b, out);
}

// round 11
// speedup vs baseline: 2.2954x; 1.4955x over previous
#include <cuda_runtime.h>
#include <cuda_fp16.h>
#include <cstdint>

// ---------------- problem constants ----------------
constexpr int cB = 32768, cS = 5, cD = 512, cE = 256, cNH = 4,
              cF = 2048, cL = 2, cC = 5;
constexpr int cBS = cB * cS;               // 163840 rows
constexpr int cZK = cS * cE;               // 1280, head input dim

// ---------------- scratch (device globals; no allocs) ----------------
__device__ __align__(16) float g_H [(size_t)cBS * cE];    // residual stream fp32
__device__ __align__(16) float g_T [(size_t)cBS * 768];   // qkv fp32
__device__ __align__(16) float g_Cb[(size_t)cBS * cE];    // pre-LN gemm out fp32
__device__ __align__(16) float g_Z1[(size_t)cB * 128];
__device__ __align__(16) float g_Z2[(size_t)cB * 64];

__device__ __align__(16) __half g_X [(size_t)cBS * cD];
__device__ __align__(16) __half g_Hh[(size_t)cBS * cE];
__device__ __align__(16) __half g_Oh[(size_t)cBS * cE];
__device__ __align__(16) __half g_Th[(size_t)cBS * cF];

// weight fp16 pool (element offsets)
constexpr size_t OFF_GPS = 0;                       // 256*512
constexpr size_t OFF_ANG = OFF_GPS + 131072;
constexpr size_t OFF_QKV = OFF_ANG + 131072;        // L*768*256
constexpr size_t OFF_OW  = OFF_QKV + 393216;        // L*256*256
constexpr size_t OFF_FF1 = OFF_OW  + 131072;        // L*2048*256
constexpr size_t OFF_FF2 = OFF_FF1 + 1048576;       // L*256*2048
constexpr size_t OFF_FC1 = OFF_FF2 + 1048576;       // 128*1280
constexpr size_t W_TOTAL = OFF_FC1 + 163840;
__device__ __align__(16) __half g_W[W_TOTAL];

// =================== helpers ===================
__device__ __forceinline__ uint32_t smem_u32(const void* p) {
    uint32_t a;
    asm("{ .reg .u64 t; cvta.to.shared.u64 t, %1; cvt.u32.u64 %0, t; }"
        : "=r"(a) : "l"(p));
    return a;
}
__device__ __forceinline__ void ldsm4(uint32_t& r0, uint32_t& r1,
                                      uint32_t& r2, uint32_t& r3, uint32_t addr) {
    asm volatile("ldmatrix.sync.aligned.m8n8.x4.shared.b16 {%0,%1,%2,%3}, [%4];"
                 : "=r"(r0), "=r"(r1), "=r"(r2), "=r"(r3) : "r"(addr));
}
__device__ __forceinline__ void mma16816h(float* d, const uint32_t* a,
                                          uint32_t b0, uint32_t b1) {
    asm volatile(
        "mma.sync.aligned.m16n8k16.row.col.f32.f16.f16.f32 "
        "{%0,%1,%2,%3}, {%4,%5,%6,%7}, {%8,%9}, {%0,%1,%2,%3};"
        : "+f"(d[0]), "+f"(d[1]), "+f"(d[2]), "+f"(d[3])
        : "r"(a[0]), "r"(a[1]), "r"(a[2]), "r"(a[3]), "r"(b0), "r"(b1));
}
__device__ __forceinline__ void cpasync16(uint32_t dst, const void* src) {
    asm volatile("cp.async.cg.shared.global [%0], [%1], 16;" :: "r"(dst), "l"(src));
}
#define CP_COMMIT() asm volatile("cp.async.commit_group;" ::: "memory")
#define CP_WAIT1()  asm volatile("cp.async.wait_group 1;" ::: "memory")

__device__ __forceinline__ uint32_t pack_h2(float x, float y) {
    __half2 h = __float22half2_rn(make_float2(x, y));
    return *(uint32_t*)&h;
}

// =================== fp32 -> fp16 converter ===================
__global__ __launch_bounds__(256) void convert_h(
    const float* __restrict__ src, __half* __restrict__ dst, size_t n4)
{
    const size_t i = (size_t)blockIdx.x * blockDim.x + threadIdx.x;
    if (i >= n4) return;
    float4 v = ((const float4*)src)[i];
    ((uint2*)dst)[i] = make_uint2(pack_h2(v.x, v.y), pack_h2(v.z, v.w));
}

// =================== tensor-core GEMM: CTA 128x128, warp tile 32x64 ================
// 8 warps as 4(M) x 2(N). single-pass fp16: C = A.W^T + bias.
// M%128==0, N%128==0, K%32==0.
constexpr int SROW = 80;                   // smem row stride (bytes)
constexpr int SBUF = 128 * SROW;           // 10240 B per operand
constexpr int STAGE_B = 2 * SBUF;          // 20480 B per stage (A, W)
constexpr int GEMM_SMEM = 2 * STAGE_B;     // 40960 B

template<bool RELU, bool PAIR>
__global__ __launch_bounds__(256, 2) void gemm_mma(
    const __half* __restrict__ A, const __half* __restrict__ W,
    const float* __restrict__ bias,
    float* __restrict__ Cf, __half* __restrict__ Ch,
    int M, int N, int K)
{
    extern __shared__ char sm[];
    const uint32_t sbase = smem_u32(sm);

    const int tid = threadIdx.x;
    const int wid = tid >> 5, lane = tid & 31;
    const int bm = blockIdx.y * 128, bn = blockIdx.x * 128;
    const int wm = (wid >> 1) * 32, wn = (wid & 1) * 64;

    // loader: thread -> row tid/2 (0..127), 16B chunks q0, q0+1 where q0=(tid&1)*2
    const int lrow = tid >> 1;
    const int q0 = (tid & 1) * 2;
    const __half* pA = A + (size_t)(bm + lrow) * K + q0 * 8;
    const __half* pW = W + (size_t)(bn + lrow) * K + q0 * 8;
    const uint32_t soff = (uint32_t)(lrow * SROW + q0 * 16);

    auto issue_stage = [&](int c, int s) {
        const uint32_t st = sbase + s * STAGE_B + soff;
        const size_t ko = (size_t)c * 32;
        cpasync16(st,               pA + ko);
        cpasync16(st + 16,          pA + ko + 8);
        cpasync16(st + SBUF,        pW + ko);
        cpasync16(st + SBUF + 16,   pW + ko + 8);
    };

    float acc[2][8][4];
#pragma unroll
    for (int i = 0; i < 2; i++)
#pragma unroll
        for (int j = 0; j < 8; j++)
#pragma unroll
            for (int k = 0; k < 4; k++) acc[i][j][k] = 0.f;

    const uint32_t a_off = (uint32_t)((wm + (lane & 15)) * SROW + (lane >> 4) * 16);
    const uint32_t w_off = (uint32_t)((wn + (lane & 7) + ((lane >> 4) & 1) * 8) * SROW
                                      + ((lane >> 3) & 1) * 16);

    const int nk = K / 32;
    issue_stage(0, 0); CP_COMMIT();
    if (nk > 1) issue_stage(1, 1);
    CP_COMMIT();

    for (int c = 0; c < nk; ++c) {
        const int s = c & 1;
        CP_WAIT1();
        __syncthreads();

        const uint32_t sA = sbase + s * STAGE_B;
        const uint32_t sW = sA + SBUF;

#pragma unroll
        for (int ks = 0; ks < 2; ++ks) {
            const uint32_t ko = ks * 32;
            uint32_t aF[2][4], bF[8][2];
#pragma unroll
            for (int mf = 0; mf < 2; mf++)
                ldsm4(aF[mf][0], aF[mf][1], aF[mf][2], aF[mf][3],
                      sA + a_off + mf * (16 * SROW) + ko);
#pragma unroll
            for (int p = 0; p < 4; p++) {
                uint32_t r0, r1, r2, r3;
                ldsm4(r0, r1, r2, r3, sW + w_off + p * (16 * SROW) + ko);
                bF[2*p][0] = r0; bF[2*p][1] = r1;
                bF[2*p+1][0] = r2; bF[2*p+1][1] = r3;
            }
#pragma unroll
            for (int mf = 0; mf < 2; mf++)
#pragma unroll
                for (int nf = 0; nf < 8; nf++)
                    mma16816h(acc[mf][nf], aF[mf], bF[nf][0], bF[nf][1]);
        }
        __syncthreads();
        if (c + 2 < nk) issue_stage(c + 2, s);
        CP_COMMIT();
    }

    // epilogue
    const int erow = (lane >> 2);
    const int ecol = (lane & 3) * 2;
#pragma unroll
    for (int nf = 0; nf < 8; nf++) {
        const int col = bn + wn + nf * 8 + ecol;
        const float2 bv = *(const float2*)&bias[col];
#pragma unroll
        for (int mf = 0; mf < 2; mf++) {
            const int r0 = bm + wm + mf * 16 + erow;
            float2 o0, o1;
            o0.x = acc[mf][nf][0] + bv.x; o0.y = acc[mf][nf][1] + bv.y;
            o1.x = acc[mf][nf][2] + bv.x; o1.y = acc[mf][nf][3] + bv.y;
            if (RELU) {
                o0.x = fmaxf(o0.x, 0.f); o0.y = fmaxf(o0.y, 0.f);
                o1.x = fmaxf(o1.x, 0.f); o1.y = fmaxf(o1.y, 0.f);
            }
            if (PAIR) {
                *(uint32_t*)&Ch[(size_t)r0 * N + col] = pack_h2(o0.x, o0.y);
                *(uint32_t*)&Ch[(size_t)(r0 + 8) * N + col] = pack_h2(o1.x, o1.y);
            } else {
                *(float2*)&Cf[(size_t)r0 * N + col] = o0;
                *(float2*)&Cf[(size_t)(r0 + 8) * N + col] = o1;
            }
        }
    }
}

// =================== small SIMT GEMM (head fc2) ===================
__global__ __launch_bounds__(256) void gemm_bias(
    const float* __restrict__ A, const float* __restrict__ W,
    const float* __restrict__ bias, float* __restrict__ C,
    int M, int N, int K)
{
    __shared__ float As[16][68];
    __shared__ float Ws[16][68];
    const int t  = threadIdx.x;
    const int bm = blockIdx.y * 64, bn = blockIdx.x * 64;
    const int tm = (t >> 4) << 2;
    const int tn = (t & 15) << 2;
    const int lr = t >> 2;
    const int lc = (t & 3) << 2;

    float acc[4][4] = {};
    const float* Ap = A + (size_t)(bm + lr) * K + lc;
    const float* Wp = W + (size_t)(bn + lr) * K + lc;

    for (int k0 = 0; k0 < K; k0 += 16) {
        float4 av = *(const float4*)(Ap + k0);
        float4 wv = (bn + lr < N) ? *(const float4*)(Wp + k0) : make_float4(0, 0, 0, 0);
        As[lc+0][lr]=av.x; As[lc+1][lr]=av.y; As[lc+2][lr]=av.z; As[lc+3][lr]=av.w;
        Ws[lc+0][lr]=wv.x; Ws[lc+1][lr]=wv.y; Ws[lc+2][lr]=wv.z; Ws[lc+3][lr]=wv.w;
        __syncthreads();
#pragma unroll
        for (int k = 0; k < 16; k++) {
            float4 a4 = *(const float4*)&As[k][tm];
            float4 w4 = *(const float4*)&Ws[k][tn];
            const float ar[4] = {a4.x, a4.y, a4.z, a4.w};
            const float wr[4] = {w4.x, w4.y, w4.z, w4.w};
#pragma unroll
            for (int r = 0; r < 4; r++)
#pragma unroll
                for (int c = 0; c < 4; c++)
                    acc[r][c] = fmaf(ar[r], wr[c], acc[r][c]);
        }
        __syncthreads();
    }
    if (bn + tn >= N) return;
    float4 bv = *(const float4*)&bias[bn + tn];
    const float bb[4] = {bv.x, bv.y, bv.z, bv.w};
#pragma unroll
    for (int r = 0; r < 4; r++) {
        float4 o; float* op = (float*)&o;
#pragma unroll
        for (int c = 0; c < 4; c++) op[c] = acc[r][c] + bb[c];
        *(float4*)&C[(size_t)(bm + tm + r) * N + bn + tn] = o;
    }
}

// =================== expert select (fp32 in, fp32 + fp16 out) ===================
__global__ __launch_bounds__(256) void select_kernel(
    const float* __restrict__ G, const float* __restrict__ A2,
    const int* __restrict__ ST, float* __restrict__ H,
    __half* __restrict__ Hh)
{
    const size_t i = (size_t)blockIdx.x * blockDim.x + threadIdx.x;  // float4 idx
    const int row = (int)(i >> 6);                                   // 64 float4/row
    const float4 v = (ST[row] == 0) ? ((const float4*)G)[i] : ((const float4*)A2)[i];
    ((float4*)H)[i] = v;
    ((uint2*)Hh)[i] = make_uint2(pack_h2(v.x, v.y), pack_h2(v.z, v.w));
}

// =================== attention: one warp per (batch, head), fp16 out ===============
__global__ __launch_bounds__(256) void attn_kernel(
    const float* __restrict__ QKV, __half* __restrict__ Oh)
{
    const int gwarp = (blockIdx.x * blockDim.x + threadIdx.x) >> 5;
    const int lane  = threadIdx.x & 31;
    if (gwarp >= cB * cNH) return;
    const int b = gwarp >> 2, h = gwarp & 3;

    const float* base = QKV + (size_t)b * cS * 768 + h * 64 + 2 * lane;
    float q[cS][2], kk[cS][2], vv[cS][2];
#pragma unroll
    for (int s = 0; s < cS; s++) {
        const float* r = base + s * 768;
        float2 qv = *(const float2*)(r);
        float2 kv = *(const float2*)(r + 256);
        float2 vw = *(const float2*)(r + 512);
        q [s][0] = qv.x; q [s][1] = qv.y;
        kk[s][0] = kv.x; kk[s][1] = kv.y;
        vv[s][0] = vw.x; vv[s][1] = vw.y;
    }
    float sc[cS][cS];
#pragma unroll
    for (int i = 0; i < cS; i++)
#pragma unroll
        for (int j = 0; j < cS; j++) {
            float p = q[i][0] * kk[j][0] + q[i][1] * kk[j][1];
#pragma unroll
            for (int o = 16; o > 0; o >>= 1) p += __shfl_xor_sync(0xFFFFFFFFu, p, o);
            sc[i][j] = p * 0.125f;
        }
#pragma unroll
    for (int i = 0; i < cS; i++) {
        float m = sc[i][0];
#pragma unroll
        for (int j = 1; j < cS; j++) m = fmaxf(m, sc[i][j]);
        float e[cS], s = 0.f;
#pragma unroll
        for (int j = 0; j < cS; j++) { e[j] = expf(sc[i][j] - m); s += e[j]; }
        const float inv = 1.f / s;
        float o0 = 0.f, o1 = 0.f;
#pragma unroll
        for (int j = 0; j < cS; j++) {
            const float a = e[j] * inv;
            o0 = fmaf(a, vv[j][0], o0);
            o1 = fmaf(a, vv[j][1], o1);
        }
        const size_t off = (size_t)(b * cS + i) * cE + h * 64 + 2 * lane;
        *(uint32_t*)&Oh[off] = pack_h2(o0, o1);
    }
}

// =================== fused residual + layernorm (fp32 + fp16 out) ===============
__global__ __launch_bounds__(256) void add_ln_kernel(
    const float* __restrict__ Hin, const float* __restrict__ Cin,
    const float* __restrict__ G, const float* __restrict__ Bv,
    float* __restrict__ Hout, __half* __restrict__ Hh)
{
    const int row  = blockIdx.x * 8 + (threadIdx.x >> 5);
    const int lane = threadIdx.x & 31;
    const size_t rb = (size_t)row * cE;

    float2 v[4];
    float s = 0.f;
#pragma unroll
    for (int i = 0; i < 4; i++) {
        const int e = i * 64 + lane * 2;
        float2 a = *(const float2*)&Hin[rb + e];
        float2 b = *(const float2*)&Cin[rb + e];
        v[i].x = a.x + b.x; v[i].y = a.y + b.y;
        s += v[i].x + v[i].y;
    }
#pragma unroll
    for (int o = 16; o > 0; o >>= 1) s += __shfl_xor_sync(0xFFFFFFFFu, s, o);
    const float mean = s * (1.f / cE);

    float vs = 0.f;
#pragma unroll
    for (int i = 0; i < 4; i++) {
        const float dx = v[i].x - mean, dy = v[i].y - mean;
        vs += dx * dx + dy * dy;
    }
#pragma unroll
    for (int o = 16; o > 0; o >>= 1) vs += __shfl_xor_sync(0xFFFFFFFFu, vs, o);
    const float rs = rsqrtf(vs * (1.f / cE) + 1e-5f);

#pragma unroll
    for (int i = 0; i < 4; i++) {
        const int e = i * 64 + lane * 2;
        const float2 g = *(const float2*)&G[e];
        const float2 b = *(const float2*)&Bv[e];
        float2 o;
        o.x = (v[i].x - mean) * rs * g.x + b.x;
        o.y = (v[i].y - mean) * rs * g.y + b.y;
        *(float2*)&Hout[rb + e] = o;
        *(uint32_t*)&Hh[rb + e] = pack_h2(o.x, o.y);
    }
}

// =================== final tiny projection ===================
__global__ __launch_bounds__(256) void out_kernel(
    const float* __restrict__ Z, const float* __restrict__ OW,
    const float* __restrict__ OB, float* __restrict__ OUT)
{
    const int b = blockIdx.x * blockDim.x + threadIdx.x;
    if (b >= cB) return;
    float acc[cC];
#pragma unroll
    for (int c = 0; c < cC; c++) acc[c] = OB[c];
    const float* zr = Z + (size_t)b * 64;
    for (int k = 0; k < 64; k++) {
        const float z = zr[k];
#pragma unroll
        for (int c = 0; c < cC; c++) acc[c] = fmaf(z, OW[c * 64 + k], acc[c]);
    }
#pragma unroll
    for (int c = 0; c < cC; c++) OUT[(size_t)b * cC + c] = acc[c];
}

// ---------------- launch ----------------
template<typename T>
static T* symaddr(const void* sym) {
    void* p = nullptr;
    cudaGetSymbolAddress(&p, sym);
    return (T*)p;
}
static void conv_w(const float* src, __half* dst, size_t n) {
    const size_t n4 = n / 4;
    convert_h<<<(unsigned)((n4 + 255) / 256), 256>>>(src, dst, n4);
}

extern "C" void kernel_launch(void* const* d_in, const int* in_sizes, int n_in,
                              void* d_out, int out_size)
{
    const float* x       = (const float*)d_in[0];
    const int*   st      = (const int*)  d_in[1];
    const float* gps_w   = (const float*)d_in[2];
    const float* gps_b   = (const float*)d_in[3];
    const float* ang_w   = (const float*)d_in[4];
    const float* ang_b   = (const float*)d_in[5];
    const float* qkv_w   = (const float*)d_in[6];
    const float* qkv_b   = (const float*)d_in[7];
    const float* attn_ow = (const float*)d_in[8];
    const float* attn_ob = (const float*)d_in[9];
    const float* ln1_g   = (const float*)d_in[10];
    const float* ln1_b   = (const float*)d_in[11];
    const float* ff1_w   = (const float*)d_in[12];
    const float* ff1_b   = (const float*)d_in[13];
    const float* ff2_w   = (const float*)d_in[14];
    const float* ff2_b   = (const float*)d_in[15];
    const float* ln2_g   = (const float*)d_in[16];
    const float* ln2_b   = (const float*)d_in[17];
    const float* fc1_w   = (const float*)d_in[18];
    const float* fc1_b   = (const float*)d_in[19];
    const float* fc2_w   = (const float*)d_in[20];
    const float* fc2_b   = (const float*)d_in[21];
    const float* out_w   = (const float*)d_in[22];
    const float* out_b   = (const float*)d_in[23];
    float* out = (float*)d_out;

    float* H  = symaddr<float>(g_H);
    float* T  = symaddr<float>(g_T);
    float* Cb = symaddr<float>(g_Cb);
    float* Z1 = symaddr<float>(g_Z1);
    float* Z2 = symaddr<float>(g_Z2);
    __half* X  = symaddr<__half>(g_X);
    __half* Hh = symaddr<__half>(g_Hh);
    __half* Oh = symaddr<__half>(g_Oh);
    __half* Th = symaddr<__half>(g_Th);
    __half* W  = symaddr<__half>(g_W);

    static bool attr_set = false;
    if (!attr_set) {
        cudaFuncSetAttribute((const void*)gemm_mma<false,false>,
                             cudaFuncAttributeMaxDynamicSharedMemorySize, GEMM_SMEM);
        cudaFuncSetAttribute((const void*)gemm_mma<true,false>,
                             cudaFuncAttributeMaxDynamicSharedMemorySize, GEMM_SMEM);
        cudaFuncSetAttribute((const void*)gemm_mma<true,true>,
                             cudaFuncAttributeMaxDynamicSharedMemorySize, GEMM_SMEM);
        attr_set = true;
    }

    // 0. convert input + weights to fp16
    conv_w(x, X, (size_t)cBS * cD);
    conv_w(gps_w,   W + OFF_GPS, 131072);
    conv_w(ang_w,   W + OFF_ANG, 131072);
    conv_w(qkv_w,   W + OFF_QKV, 393216);
    conv_w(attn_ow, W + OFF_OW,  131072);
    conv_w(ff1_w,   W + OFF_FF1, 1048576);
    conv_w(ff2_w,   W + OFF_FF2, 1048576);
    conv_w(fc1_w,   W + OFF_FC1, 163840);

    const int MT = cBS / 128;   // 1280 row tiles
    float* G  = T;                      // expert outputs (fp32 scratch)
    float* A2 = T + (size_t)cBS * cE;   // fits in g_T ([BS,768])

    // 1. dual-expert embed + select
    gemm_mma<true,false><<<dim3(cE/128, MT), 256, GEMM_SMEM>>>(
        X, W + OFF_GPS, gps_b, G, nullptr, cBS, cE, cD);
    gemm_mma<true,false><<<dim3(cE/128, MT), 256, GEMM_SMEM>>>(
        X, W + OFF_ANG, ang_b, A2, nullptr, cBS, cE, cD);
    select_kernel<<<(cBS * cE / 4) / 256, 256>>>(G, A2, st, H, Hh);

    // 2. transformer layers
    for (int l = 0; l < cL; l++) {
        const __half* qw  = W + OFF_QKV + (size_t)l * 768 * cE;
        const __half* ow  = W + OFF_OW  + (size_t)l * cE * cE;
        const __half* f1w = W + OFF_FF1 + (size_t)l * cF * cE;
        const __half* f2w = W + OFF_FF2 + (size_t)l * cE * cF;
        const float* qb  = qkv_b   + (size_t)l * 3 * cE;
        const float* ob  = attn_ob + (size_t)l * cE;
        const float* f1b = ff1_b   + (size_t)l * cF;
        const float* f2b = ff2_b   + (size_t)l * cE;

        gemm_mma<false,false><<<dim3(768/128, MT), 256, GEMM_SMEM>>>(
            Hh, qw, qb, T, nullptr, cBS, 768, cE);
        attn_kernel<<<(cB * cNH * 32) / 256, 256>>>(T, Oh);
        gemm_mma<false,false><<<dim3(cE/128, MT), 256, GEMM_SMEM>>>(
            Oh, ow, ob, Cb, nullptr, cBS, cE, cE);
        add_ln_kernel<<<cBS / 8, 256>>>(H, Cb, ln1_g + l * cE, ln1_b + l * cE, H, Hh);
        gemm_mma<true,true><<<dim3(cF/128, MT), 256, GEMM_SMEM>>>(
            Hh, f1w, f1b, nullptr, Th, cBS, cF, cE);
        gemm_mma<false,false><<<dim3(cE/128, MT), 256, GEMM_SMEM>>>(
            Th, f2w, f2b, Cb, nullptr, cBS, cE, cF);
        add_ln_kernel<<<cBS / 8, 256>>>(H, Cb, ln2_g + l * cE, ln2_b + l * cE, H, Hh);
    }

    // 3. head: Hh viewed as [B,1280]
    gemm_mma<false,false><<<dim3(1, cB/128), 256, GEMM_SMEM>>>(
        Hh, W + OFF_FC1, fc1_b, Z1, nullptr, cB, 128, cZK);
    gemm_bias<<<dim3(1, cB/64), 256>>>(Z1, fc2_w, fc2_b, Z2, cB, 64, 128);
    out_kernel<<<cB / 256, 256>>>(Z2, out_w, out_b, out);
}

// round 12
// speedup vs baseline: 2.3416x; 1.0201x over previous
#include <cuda_runtime.h>
#include <cuda_fp16.h>
#include <cstdint>

// ---------------- problem constants ----------------
constexpr int cB = 32768, cS = 5, cD = 512, cE = 256, cNH = 4,
              cF = 2048, cL = 2, cC = 5;
constexpr int cBS = cB * cS;               // 163840 rows
constexpr int cZK = cS * cE;               // 1280, head input dim

// ---------------- scratch (device globals; no allocs) ----------------
__device__ __align__(16) float g_H [(size_t)cBS * cE];    // residual stream fp32 (+embed G)
__device__ __align__(16) float g_Cb[(size_t)cBS * cE];    // embed A2 scratch fp32
__device__ __align__(16) float g_Z1[(size_t)cB * 128];
__device__ __align__(16) float g_Z2[(size_t)cB * 64];

__device__ __align__(16) __half g_X  [(size_t)cBS * cD];
__device__ __align__(16) __half g_Hh [(size_t)cBS * cE];
__device__ __align__(16) __half g_Oh [(size_t)cBS * cE];
__device__ __align__(16) __half g_T  [(size_t)cBS * 768];  // qkv fp16
__device__ __align__(16) __half g_Th [(size_t)cBS * cF];   // ff1 out fp16
__device__ __align__(16) __half g_Cbh[(size_t)cBS * cE];   // pre-LN gemm out fp16

// weight fp16 pool (element offsets)
constexpr size_t OFF_GPS = 0;                       // 256*512
constexpr size_t OFF_ANG = OFF_GPS + 131072;
constexpr size_t OFF_QKV = OFF_ANG + 131072;        // L*768*256
constexpr size_t OFF_OW  = OFF_QKV + 393216;        // L*256*256
constexpr size_t OFF_FF1 = OFF_OW  + 131072;        // L*2048*256
constexpr size_t OFF_FF2 = OFF_FF1 + 1048576;       // L*256*2048
constexpr size_t OFF_FC1 = OFF_FF2 + 1048576;       // 128*1280
constexpr size_t W_TOTAL = OFF_FC1 + 163840;
__device__ __align__(16) __half g_W[W_TOTAL];

// =================== helpers ===================
__device__ __forceinline__ uint32_t smem_u32(const void* p) {
    uint32_t a;
    asm("{ .reg .u64 t; cvta.to.shared.u64 t, %1; cvt.u32.u64 %0, t; }"
        : "=r"(a) : "l"(p));
    return a;
}
__device__ __forceinline__ void ldsm4(uint32_t& r0, uint32_t& r1,
                                      uint32_t& r2, uint32_t& r3, uint32_t addr) {
    asm volatile("ldmatrix.sync.aligned.m8n8.x4.shared.b16 {%0,%1,%2,%3}, [%4];"
                 : "=r"(r0), "=r"(r1), "=r"(r2), "=r"(r3) : "r"(addr));
}
__device__ __forceinline__ void mma16816h(float* d, const uint32_t* a,
                                          uint32_t b0, uint32_t b1) {
    asm volatile(
        "mma.sync.aligned.m16n8k16.row.col.f32.f16.f16.f32 "
        "{%0,%1,%2,%3}, {%4,%5,%6,%7}, {%8,%9}, {%0,%1,%2,%3};"
        : "+f"(d[0]), "+f"(d[1]), "+f"(d[2]), "+f"(d[3])
        : "r"(a[0]), "r"(a[1]), "r"(a[2]), "r"(a[3]), "r"(b0), "r"(b1));
}
__device__ __forceinline__ void cpasync16(uint32_t dst, const void* src) {
    asm volatile("cp.async.cg.shared.global [%0], [%1], 16;" :: "r"(dst), "l"(src));
}
#define CP_COMMIT() asm volatile("cp.async.commit_group;" ::: "memory")
#define CP_WAIT2()  asm volatile("cp.async.wait_group 2;" ::: "memory")

__device__ __forceinline__ uint32_t pack_h2(float x, float y) {
    __half2 h = __float22half2_rn(make_float2(x, y));
    return *(uint32_t*)&h;
}
__device__ __forceinline__ float2 unpack_h2(uint32_t u) {
    return __half22float2(*(__half2*)&u);
}

// =================== fp32 -> fp16 converter ===================
__global__ __launch_bounds__(256) void convert_h(
    const float* __restrict__ src, __half* __restrict__ dst, size_t n4)
{
    const size_t i = (size_t)blockIdx.x * blockDim.x + threadIdx.x;
    if (i >= n4) return;
    float4 v = ((const float4*)src)[i];
    ((uint2*)dst)[i] = make_uint2(pack_h2(v.x, v.y), pack_h2(v.z, v.w));
}

// =================== tensor-core GEMM: CTA 128x128, warp tile 32x64 ================
// 8 warps as 4(M) x 2(N). single-pass fp16: C = A.W^T + bias. 3-stage cp.async.
// M%128==0, N%128==0, K%32==0, K>=96.
constexpr int SROW = 80;                   // smem row stride (bytes)
constexpr int SBUF = 128 * SROW;           // 10240 B per operand
constexpr int STAGE_B = 2 * SBUF;          // 20480 B per stage (A, W)
constexpr int NSTG = 3;
constexpr int GEMM_SMEM = NSTG * STAGE_B;  // 61440 B

template<bool RELU, bool PAIR>
__global__ __launch_bounds__(256, 2) void gemm_mma(
    const __half* __restrict__ A, const __half* __restrict__ W,
    const float* __restrict__ bias,
    float* __restrict__ Cf, __half* __restrict__ Ch,
    int M, int N, int K)
{
    extern __shared__ char sm[];
    const uint32_t sbase = smem_u32(sm);

    const int tid = threadIdx.x;
    const int wid = tid >> 5, lane = tid & 31;
    const int bm = blockIdx.y * 128, bn = blockIdx.x * 128;
    const int wm = (wid >> 1) * 32, wn = (wid & 1) * 64;

    // loader: thread -> row tid/2 (0..127), 16B chunks q0, q0+1 where q0=(tid&1)*2
    const int lrow = tid >> 1;
    const int q0 = (tid & 1) * 2;
    const __half* pA = A + (size_t)(bm + lrow) * K + q0 * 8;
    const __half* pW = W + (size_t)(bn + lrow) * K + q0 * 8;
    const uint32_t soff = (uint32_t)(lrow * SROW + q0 * 16);

    auto issue_stage = [&](int c, int s) {
        const uint32_t st = sbase + s * STAGE_B + soff;
        const size_t ko = (size_t)c * 32;
        cpasync16(st,               pA + ko);
        cpasync16(st + 16,          pA + ko + 8);
        cpasync16(st + SBUF,        pW + ko);
        cpasync16(st + SBUF + 16,   pW + ko + 8);
    };

    float acc[2][8][4];
#pragma unroll
    for (int i = 0; i < 2; i++)
#pragma unroll
        for (int j = 0; j < 8; j++)
#pragma unroll
            for (int k = 0; k < 4; k++) acc[i][j][k] = 0.f;

    const uint32_t a_off = (uint32_t)((wm + (lane & 15)) * SROW + (lane >> 4) * 16);
    const uint32_t w_off = (uint32_t)((wn + (lane & 7) + ((lane >> 4) & 1) * 8) * SROW
                                      + ((lane >> 3) & 1) * 16);

    const int nk = K / 32;
    issue_stage(0, 0); CP_COMMIT();
    issue_stage(1, 1); CP_COMMIT();
    issue_stage(2, 2); CP_COMMIT();

    int s = 0;
    for (int c = 0; c < nk; ++c) {
        CP_WAIT2();
        __syncthreads();

        const uint32_t sA = sbase + s * STAGE_B;
        const uint32_t sW = sA + SBUF;

#pragma unroll
        for (int ks = 0; ks < 2; ++ks) {
            const uint32_t ko = ks * 32;
            uint32_t aF[2][4], bF[8][2];
#pragma unroll
            for (int mf = 0; mf < 2; mf++)
                ldsm4(aF[mf][0], aF[mf][1], aF[mf][2], aF[mf][3],
                      sA + a_off + mf * (16 * SROW) + ko);
#pragma unroll
            for (int p = 0; p < 4; p++) {
                uint32_t r0, r1, r2, r3;
                ldsm4(r0, r1, r2, r3, sW + w_off + p * (16 * SROW) + ko);
                bF[2*p][0] = r0; bF[2*p][1] = r1;
                bF[2*p+1][0] = r2; bF[2*p+1][1] = r3;
            }
#pragma unroll
            for (int mf = 0; mf < 2; mf++)
#pragma unroll
                for (int nf = 0; nf < 8; nf++)
                    mma16816h(acc[mf][nf], aF[mf], bF[nf][0], bF[nf][1]);
        }
        __syncthreads();
        if (c + NSTG < nk) issue_stage(c + NSTG, s);
        CP_COMMIT();
        s = (s + 1 == NSTG) ? 0 : s + 1;
    }

    // epilogue
    const int erow = (lane >> 2);
    const int ecol = (lane & 3) * 2;
#pragma unroll
    for (int nf = 0; nf < 8; nf++) {
        const int col = bn + wn + nf * 8 + ecol;
        const float2 bv = *(const float2*)&bias[col];
#pragma unroll
        for (int mf = 0; mf < 2; mf++) {
            const int r0 = bm + wm + mf * 16 + erow;
            float2 o0, o1;
            o0.x = acc[mf][nf][0] + bv.x; o0.y = acc[mf][nf][1] + bv.y;
            o1.x = acc[mf][nf][2] + bv.x; o1.y = acc[mf][nf][3] + bv.y;
            if (RELU) {
                o0.x = fmaxf(o0.x, 0.f); o0.y = fmaxf(o0.y, 0.f);
                o1.x = fmaxf(o1.x, 0.f); o1.y = fmaxf(o1.y, 0.f);
            }
            if (PAIR) {
                *(uint32_t*)&Ch[(size_t)r0 * N + col] = pack_h2(o0.x, o0.y);
                *(uint32_t*)&Ch[(size_t)(r0 + 8) * N + col] = pack_h2(o1.x, o1.y);
            } else {
                *(float2*)&Cf[(size_t)r0 * N + col] = o0;
                *(float2*)&Cf[(size_t)(r0 + 8) * N + col] = o1;
            }
        }
    }
}

// =================== small SIMT GEMM (head fc2) ===================
__global__ __launch_bounds__(256) void gemm_bias(
    const float* __restrict__ A, const float* __restrict__ W,
    const float* __restrict__ bias, float* __restrict__ C,
    int M, int N, int K)
{
    __shared__ float As[16][68];
    __shared__ float Ws[16][68];
    const int t  = threadIdx.x;
    const int bm = blockIdx.y * 64, bn = blockIdx.x * 64;
    const int tm = (t >> 4) << 2;
    const int tn = (t & 15) << 2;
    const int lr = t >> 2;
    const int lc = (t & 3) << 2;

    float acc[4][4] = {};
    const float* Ap = A + (size_t)(bm + lr) * K + lc;
    const float* Wp = W + (size_t)(bn + lr) * K + lc;

    for (int k0 = 0; k0 < K; k0 += 16) {
        float4 av = *(const float4*)(Ap + k0);
        float4 wv = (bn + lr < N) ? *(const float4*)(Wp + k0) : make_float4(0, 0, 0, 0);
        As[lc+0][lr]=av.x; As[lc+1][lr]=av.y; As[lc+2][lr]=av.z; As[lc+3][lr]=av.w;
        Ws[lc+0][lr]=wv.x; Ws[lc+1][lr]=wv.y; Ws[lc+2][lr]=wv.z; Ws[lc+3][lr]=wv.w;
        __syncthreads();
#pragma unroll
        for (int k = 0; k < 16; k++) {
            float4 a4 = *(const float4*)&As[k][tm];
            float4 w4 = *(const float4*)&Ws[k][tn];
            const float ar[4] = {a4.x, a4.y, a4.z, a4.w};
            const float wr[4] = {w4.x, w4.y, w4.z, w4.w};
#pragma unroll
            for (int r = 0; r < 4; r++)
#pragma unroll
                for (int c = 0; c < 4; c++)
                    acc[r][c] = fmaf(ar[r], wr[c], acc[r][c]);
        }
        __syncthreads();
    }
    if (bn + tn >= N) return;
    float4 bv = *(const float4*)&bias[bn + tn];
    const float bb[4] = {bv.x, bv.y, bv.z, bv.w};
#pragma unroll
    for (int r = 0; r < 4; r++) {
        float4 o; float* op = (float*)&o;
#pragma unroll
        for (int c = 0; c < 4; c++) op[c] = acc[r][c] + bb[c];
        *(float4*)&C[(size_t)(bm + tm + r) * N + bn + tn] = o;
    }
}

// =================== expert select (fp32 in, fp32 + fp16 out) ===================
__global__ __launch_bounds__(256) void select_kernel(
    const float* __restrict__ G, const float* __restrict__ A2,
    const int* __restrict__ ST, float* __restrict__ H,
    __half* __restrict__ Hh)
{
    const size_t i = (size_t)blockIdx.x * blockDim.x + threadIdx.x;  // float4 idx
    const int row = (int)(i >> 6);                                   // 64 float4/row
    const float4 v = (ST[row] == 0) ? ((const float4*)G)[i] : ((const float4*)A2)[i];
    ((float4*)H)[i] = v;
    ((uint2*)Hh)[i] = make_uint2(pack_h2(v.x, v.y), pack_h2(v.z, v.w));
}

// =================== attention: one warp per (batch, head), fp16 in/out =============
__global__ __launch_bounds__(256) void attn_kernel(
    const __half* __restrict__ QKV, __half* __restrict__ Oh)
{
    const int gwarp = (blockIdx.x * blockDim.x + threadIdx.x) >> 5;
    const int lane  = threadIdx.x & 31;
    if (gwarp >= cB * cNH) return;
    const int b = gwarp >> 2, h = gwarp & 3;

    const __half* base = QKV + (size_t)b * cS * 768 + h * 64 + 2 * lane;
    float q[cS][2], kk[cS][2], vv[cS][2];
#pragma unroll
    for (int s = 0; s < cS; s++) {
        const __half* r = base + s * 768;
        float2 qv = unpack_h2(*(const uint32_t*)(r));
        float2 kv = unpack_h2(*(const uint32_t*)(r + 256));
        float2 vw = unpack_h2(*(const uint32_t*)(r + 512));
        q [s][0] = qv.x; q [s][1] = qv.y;
        kk[s][0] = kv.x; kk[s][1] = kv.y;
        vv[s][0] = vw.x; vv[s][1] = vw.y;
    }
    float sc[cS][cS];
#pragma unroll
    for (int i = 0; i < cS; i++)
#pragma unroll
        for (int j = 0; j < cS; j++) {
            float p = q[i][0] * kk[j][0] + q[i][1] * kk[j][1];
#pragma unroll
            for (int o = 16; o > 0; o >>= 1) p += __shfl_xor_sync(0xFFFFFFFFu, p, o);
            sc[i][j] = p * 0.125f;
        }
#pragma unroll
    for (int i = 0; i < cS; i++) {
        float m = sc[i][0];
#pragma unroll
        for (int j = 1; j < cS; j++) m = fmaxf(m, sc[i][j]);
        float e[cS], s = 0.f;
#pragma unroll
        for (int j = 0; j < cS; j++) { e[j] = expf(sc[i][j] - m); s += e[j]; }
        const float inv = 1.f / s;
        float o0 = 0.f, o1 = 0.f;
#pragma unroll
        for (int j = 0; j < cS; j++) {
            const float a = e[j] * inv;
            o0 = fmaf(a, vv[j][0], o0);
            o1 = fmaf(a, vv[j][1], o1);
        }
        const size_t off = (size_t)(b * cS + i) * cE + h * 64 + 2 * lane;
        *(uint32_t*)&Oh[off] = pack_h2(o0, o1);
    }
}

// =================== fused residual + layernorm (H fp32, C fp16 in) ===============
__global__ __launch_bounds__(256) void add_ln_kernel(
    const float* __restrict__ Hin, const __half* __restrict__ Cin,
    const float* __restrict__ G, const float* __restrict__ Bv,
    float* __restrict__ Hout, __half* __restrict__ Hh)
{
    const int row  = blockIdx.x * 8 + (threadIdx.x >> 5);
    const int lane = threadIdx.x & 31;
    const size_t rb = (size_t)row * cE;

    float2 v[4];
    float s = 0.f;
#pragma unroll
    for (int i = 0; i < 4; i++) {
        const int e = i * 64 + lane * 2;
        float2 a = *(const float2*)&Hin[rb + e];
        float2 b = unpack_h2(*(const uint32_t*)&Cin[rb + e]);
        v[i].x = a.x + b.x; v[i].y = a.y + b.y;
        s += v[i].x + v[i].y;
    }
#pragma unroll
    for (int o = 16; o > 0; o >>= 1) s += __shfl_xor_sync(0xFFFFFFFFu, s, o);
    const float mean = s * (1.f / cE);

    float vs = 0.f;
#pragma unroll
    for (int i = 0; i < 4; i++) {
        const float dx = v[i].x - mean, dy = v[i].y - mean;
        vs += dx * dx + dy * dy;
    }
#pragma unroll
    for (int o = 16; o > 0; o >>= 1) vs += __shfl_xor_sync(0xFFFFFFFFu, vs, o);
    const float rs = rsqrtf(vs * (1.f / cE) + 1e-5f);

#pragma unroll
    for (int i = 0; i < 4; i++) {
        const int e = i * 64 + lane * 2;
        const float2 g = *(const float2*)&G[e];
        const float2 b = *(const float2*)&Bv[e];
        float2 o;
        o.x = (v[i].x - mean) * rs * g.x + b.x;
        o.y = (v[i].y - mean) * rs * g.y + b.y;
        *(float2*)&Hout[rb + e] = o;
        *(uint32_t*)&Hh[rb + e] = pack_h2(o.x, o.y);
    }
}

// =================== final tiny projection ===================
__global__ __launch_bounds__(256) void out_kernel(
    const float* __restrict__ Z, const float* __restrict__ OW,
    const float* __restrict__ OB, float* __restrict__ OUT)
{
    const int b = blockIdx.x * blockDim.x + threadIdx.x;
    if (b >= cB) return;
    float acc[cC];
#pragma unroll
    for (int c = 0; c < cC; c++) acc[c] = OB[c];
    const float* zr = Z + (size_t)b * 64;
    for (int k = 0; k < 64; k++) {
        const float z = zr[k];
#pragma unroll
        for (int c = 0; c < cC; c++) acc[c] = fmaf(z, OW[c * 64 + k], acc[c]);
    }
#pragma unroll
    for (int c = 0; c < cC; c++) OUT[(size_t)b * cC + c] = acc[c];
}

// ---------------- launch ----------------
template<typename T>
static T* symaddr(const void* sym) {
    void* p = nullptr;
    cudaGetSymbolAddress(&p, sym);
    return (T*)p;
}
static void conv_w(const float* src, __half* dst, size_t n) {
    const size_t n4 = n / 4;
    convert_h<<<(unsigned)((n4 + 255) / 256), 256>>>(src, dst, n4);
}

extern "C" void kernel_launch(void* const* d_in, const int* in_sizes, int n_in,
                              void* d_out, int out_size)
{
    const float* x       = (const float*)d_in[0];
    const int*   st      = (const int*)  d_in[1];
    const float* gps_w   = (const float*)d_in[2];
    const float* gps_b   = (const float*)d_in[3];
    const float* ang_w   = (const float*)d_in[4];
    const float* ang_b   = (const float*)d_in[5];
    const float* qkv_w   = (const float*)d_in[6];
    const float* qkv_b   = (const float*)d_in[7];
    const float* attn_ow = (const float*)d_in[8];
    const float* attn_ob = (const float*)d_in[9];
    const float* ln1_g   = (const float*)d_in[10];
    const float* ln1_b   = (const float*)d_in[11];
    const float* ff1_w   = (const float*)d_in[12];
    const float* ff1_b   = (const float*)d_in[13];
    const float* ff2_w   = (const float*)d_in[14];
    const float* ff2_b   = (const float*)d_in[15];
    const float* ln2_g   = (const float*)d_in[16];
    const float* ln2_b   = (const float*)d_in[17];
    const float* fc1_w   = (const float*)d_in[18];
    const float* fc1_b   = (const float*)d_in[19];
    const float* fc2_w   = (const float*)d_in[20];
    const float* fc2_b   = (const float*)d_in[21];
    const float* out_w   = (const float*)d_in[22];
    const float* out_b   = (const float*)d_in[23];
    float* out = (float*)d_out;

    float* H   = symaddr<float>(g_H);
    float* Cbf = symaddr<float>(g_Cb);
    float* Z1  = symaddr<float>(g_Z1);
    float* Z2  = symaddr<float>(g_Z2);
    __half* X   = symaddr<__half>(g_X);
    __half* Hh  = symaddr<__half>(g_Hh);
    __half* Oh  = symaddr<__half>(g_Oh);
    __half* T   = symaddr<__half>(g_T);
    __half* Th  = symaddr<__half>(g_Th);
    __half* Cbh = symaddr<__half>(g_Cbh);
    __half* W   = symaddr<__half>(g_W);

    static bool attr_set = false;
    if (!attr_set) {
        cudaFuncSetAttribute((const void*)gemm_mma<false,false>,
                             cudaFuncAttributeMaxDynamicSharedMemorySize, GEMM_SMEM);
        cudaFuncSetAttribute((const void*)gemm_mma<true,false>,
                             cudaFuncAttributeMaxDynamicSharedMemorySize, GEMM_SMEM);
        cudaFuncSetAttribute((const void*)gemm_mma<false,true>,
                             cudaFuncAttributeMaxDynamicSharedMemorySize, GEMM_SMEM);
        cudaFuncSetAttribute((const void*)gemm_mma<true,true>,
                             cudaFuncAttributeMaxDynamicSharedMemorySize, GEMM_SMEM);
        attr_set = true;
    }

    // 0. convert input + weights to fp16
    conv_w(x, X, (size_t)cBS * cD);
    conv_w(gps_w,   W + OFF_GPS, 131072);
    conv_w(ang_w,   W + OFF_ANG, 131072);
    conv_w(qkv_w,   W + OFF_QKV, 393216);
    conv_w(attn_ow, W + OFF_OW,  131072);
    conv_w(ff1_w,   W + OFF_FF1, 1048576);
    conv_w(ff2_w,   W + OFF_FF2, 1048576);
    conv_w(fc1_w,   W + OFF_FC1, 163840);

    const int MT = cBS / 128;   // 1280 row tiles

    // 1. dual-expert embed + select (G -> g_H, A2 -> g_Cb; select elementwise-aliased)
    gemm_mma<true,false><<<dim3(cE/128, MT), 256, GEMM_SMEM>>>(
        X, W + OFF_GPS, gps_b, H, nullptr, cBS, cE, cD);
    gemm_mma<true,false><<<dim3(cE/128, MT), 256, GEMM_SMEM>>>(
        X, W + OFF_ANG, ang_b, Cbf, nullptr, cBS, cE, cD);
    select_kernel<<<(cBS * cE / 4) / 256, 256>>>(H, Cbf, st, H, Hh);

    // 2. transformer layers
    for (int l = 0; l < cL; l++) {
        const __half* qw  = W + OFF_QKV + (size_t)l * 768 * cE;
        const __half* ow  = W + OFF_OW  + (size_t)l * cE * cE;
        const __half* f1w = W + OFF_FF1 + (size_t)l * cF * cE;
        const __half* f2w = W + OFF_FF2 + (size_t)l * cE * cF;
        const float* qb  = qkv_b   + (size_t)l * 3 * cE;
        const float* ob  = attn_ob + (size_t)l * cE;
        const float* f1b = ff1_b   + (size_t)l * cF;
        const float* f2b = ff2_b   + (size_t)l * cE;

        gemm_mma<false,true><<<dim3(768/128, MT), 256, GEMM_SMEM>>>(
            Hh, qw, qb, nullptr, T, cBS, 768, cE);
        attn_kernel<<<(cB * cNH * 32) / 256, 256>>>(T, Oh);
        gemm_mma<false,true><<<dim3(cE/128, MT), 256, GEMM_SMEM>>>(
            Oh, ow, ob, nullptr, Cbh, cBS, cE, cE);
        add_ln_kernel<<<cBS / 8, 256>>>(H, Cbh, ln1_g + l * cE, ln1_b + l * cE, H, Hh);
        gemm_mma<true,true><<<dim3(cF/128, MT), 256, GEMM_SMEM>>>(
            Hh, f1w, f1b, nullptr, Th, cBS, cF, cE);
        gemm_mma<false,true><<<dim3(cE/128, MT), 256, GEMM_SMEM>>>(
            Th, f2w, f2b, nullptr, Cbh, cBS, cE, cF);
        add_ln_kernel<<<cBS / 8, 256>>>(H, Cbh, ln2_g + l * cE, ln2_b + l * cE, H, Hh);
    }

    // 3. head: Hh viewed as [B,1280]
    gemm_mma<false,false><<<dim3(1, cB/128), 256, GEMM_SMEM>>>(
        Hh, W + OFF_FC1, fc1_b, Z1, nullptr, cB, 128, cZK);
    gemm_bias<<<dim3(1, cB/64), 256>>>(Z1, fc2_w, fc2_b, Z2, cB, 64, 128);
    out_kernel<<<cB / 256, 256>>>(Z2, out_w, out_b, out);
}